// round 1
// baseline (speedup 1.0000x reference)
#include <cuda_runtime.h>
#include <math.h>

#define NROWS 16384
#define NIN   2048
#define NCLS  100

// Scratch: holds z after GEMM1, overwritten row-by-row with warped values.
static __device__ float g_buf[(size_t)NROWS * NIN];

// ---------------------------------------------------------------------------
// GEMM1: C[m,n] = sum_k A[m,k] * W[n,k] + bias[n]
// A: [NROWS, NIN] row-major, W: [NIN, NIN] row-major (both K-major -> TN GEMM)
// Tile 128x128x16, 256 threads, 8x8 per thread in split (4+4) layout for
// conflict-free LDS.128 reads.
// ---------------------------------------------------------------------------
__global__ void __launch_bounds__(256)
gemm1_kernel(const float* __restrict__ A, const float* __restrict__ W,
             const float* __restrict__ bias)
{
    const int K = NIN;
    __shared__ float As[16][132];
    __shared__ float Bs[16][132];

    const int tid = threadIdx.x;
    const int bm = blockIdx.y * 128;
    const int bn = blockIdx.x * 128;
    const int tx = tid & 15;
    const int ty = tid >> 4;

    float acc[8][8] = {};

    for (int k0 = 0; k0 < K; k0 += 16) {
        #pragma unroll
        for (int i = 0; i < 2; ++i) {
            int f = tid + i * 256;       // 512 float4 per 128x16 tile
            int m = f >> 2;
            int k4 = (f & 3) << 2;
            float4 va = *(const float4*)(A + (size_t)(bm + m) * K + k0 + k4);
            As[k4 + 0][m] = va.x; As[k4 + 1][m] = va.y;
            As[k4 + 2][m] = va.z; As[k4 + 3][m] = va.w;
            float4 vb = *(const float4*)(W + (size_t)(bn + m) * K + k0 + k4);
            Bs[k4 + 0][m] = vb.x; Bs[k4 + 1][m] = vb.y;
            Bs[k4 + 2][m] = vb.z; Bs[k4 + 3][m] = vb.w;
        }
        __syncthreads();

        #pragma unroll
        for (int k = 0; k < 16; ++k) {
            float a[8], b[8];
            *(float4*)(a)     = *(const float4*)&As[k][ty * 4];
            *(float4*)(a + 4) = *(const float4*)&As[k][64 + ty * 4];
            *(float4*)(b)     = *(const float4*)&Bs[k][tx * 4];
            *(float4*)(b + 4) = *(const float4*)&Bs[k][64 + tx * 4];
            #pragma unroll
            for (int i = 0; i < 8; ++i)
                #pragma unroll
                for (int j = 0; j < 8; ++j)
                    acc[i][j] = fmaf(a[i], b[j], acc[i][j]);
        }
        __syncthreads();
    }

    // Epilogue: add bias, store. Rows/cols come in two groups of 4 (split layout).
    #pragma unroll
    for (int ri = 0; ri < 2; ++ri) {
        #pragma unroll
        for (int i = 0; i < 4; ++i) {
            int m = bm + ri * 64 + ty * 4 + i;
            #pragma unroll
            for (int cj = 0; cj < 2; ++cj) {
                int n = bn + cj * 64 + tx * 4;
                float4 v;
                v.x = acc[ri * 4 + i][cj * 4 + 0] + bias[n + 0];
                v.y = acc[ri * 4 + i][cj * 4 + 1] + bias[n + 1];
                v.z = acc[ri * 4 + i][cj * 4 + 2] + bias[n + 2];
                v.w = acc[ri * 4 + i][cj * 4 + 3] + bias[n + 3];
                *(float4*)(g_buf + (size_t)m * NIN + n) = v;
            }
        }
    }
}

// ---------------------------------------------------------------------------
// Row-wise: softmax -> cumsum (fp64 scan) -> interp on uniform knot grid.
// One block (256 threads) per row; z read from g_buf, warped written back.
// ---------------------------------------------------------------------------
__global__ void __launch_bounds__(256)
warp_rows_kernel(const float* __restrict__ X)
{
    __shared__ float  sx[NIN];
    __shared__ float  sz[NIN];
    __shared__ float  wred[8];
    __shared__ double wtot[8];

    const int row  = blockIdx.x;
    const int t    = threadIdx.x;
    const int lane = t & 31;
    const int wid  = t >> 5;
    const float* xr = X + (size_t)row * NIN;
    float* zr = g_buf + (size_t)row * NIN;

    for (int i = t; i < NIN; i += 256) { sx[i] = xr[i]; sz[i] = zr[i]; }
    __syncthreads();

    // row max
    float mx = -INFINITY;
    for (int i = t; i < NIN; i += 256) mx = fmaxf(mx, sz[i]);
    #pragma unroll
    for (int d = 16; d; d >>= 1) mx = fmaxf(mx, __shfl_xor_sync(0xffffffffu, mx, d));
    if (lane == 0) wred[wid] = mx;
    __syncthreads();
    float bmax = wred[0];
    #pragma unroll
    for (int i = 1; i < 8; ++i) bmax = fmaxf(bmax, wred[i]);

    // local exp + fp64 inclusive cumsum over this thread's 8 contiguous elems
    const int base = t * 8;
    double csum[8];
    double run = 0.0;
    #pragma unroll
    for (int i = 0; i < 8; ++i) {
        float e = expf(sz[base + i] - bmax);
        run += (double)e;
        csum[i] = run;
    }

    // block-wide fp64 scan of per-thread sums
    double v = run;
    #pragma unroll
    for (int d = 1; d < 32; d <<= 1) {
        double u = __shfl_up_sync(0xffffffffu, v, d);
        if (lane >= d) v += u;
    }
    if (lane == 31) wtot[wid] = v;
    __syncthreads();
    double total = 0.0, woff = 0.0;
    #pragma unroll
    for (int i = 0; i < 8; ++i) {         // fixed order: identical on all threads
        if (i == wid) woff = total;
        total += wtot[i];
    }
    const double toff = woff + (v - run); // exclusive prefix for this thread
    const double inv  = 1.0 / total;

    // interp on uniform grid xs = linspace(0,1,NIN): pos = gamma*(NIN-1)
    #pragma unroll
    for (int i = 0; i < 8; ++i) {
        double pos = (toff + csum[i]) * inv * (double)(NIN - 1);
        pos = fmin(fmax(pos, 0.0), (double)(NIN - 1));
        int idx = (int)pos;
        if (idx > NIN - 2) idx = NIN - 2;
        float w  = (float)(pos - (double)idx);
        float y0 = sx[idx], y1 = sx[idx + 1];
        zr[base + i] = fmaf(w, y1 - y0, y0);
    }
}

// ---------------------------------------------------------------------------
// GEMM2: out[r,c] = sum_k warped[r,k] * F[c,k] + fb[c]
// Tile: 64 rows x 112 cols (covers NCLS=100) x 32 K; 256 threads, 4x7/thread.
// ---------------------------------------------------------------------------
__global__ void __launch_bounds__(256)
gemm2_kernel(const float* __restrict__ F, const float* __restrict__ fb,
             float* __restrict__ out)
{
    __shared__ float As[32][68];
    __shared__ float Bs[32][113];

    const int tid  = threadIdx.x;
    const int row0 = blockIdx.x * 64;
    const int tx   = tid & 15;
    const int ty   = tid >> 4;

    float acc[4][7] = {};

    for (int k0 = 0; k0 < NIN; k0 += 32) {
        #pragma unroll
        for (int i = 0; i < 2; ++i) {
            int f  = tid + i * 256;      // 512 float4 = 64x32 tile
            int r  = f >> 3;
            int k4 = (f & 7) << 2;
            float4 v = *(const float4*)(g_buf + (size_t)(row0 + r) * NIN + k0 + k4);
            As[k4 + 0][r] = v.x; As[k4 + 1][r] = v.y;
            As[k4 + 2][r] = v.z; As[k4 + 3][r] = v.w;
        }
        #pragma unroll
        for (int i = 0; i < 14; ++i) {   // 3584 = 112*32 scalars
            int f  = tid + i * 256;
            int c  = f >> 5;
            int kk = f & 31;
            Bs[kk][c] = (c < NCLS) ? F[(size_t)c * NIN + k0 + kk] : 0.0f;
        }
        __syncthreads();

        #pragma unroll
        for (int k = 0; k < 32; ++k) {
            float a[4];
            *(float4*)a = *(const float4*)&As[k][ty * 4];
            float b[7];
            #pragma unroll
            for (int j = 0; j < 7; ++j) b[j] = Bs[k][tx * 7 + j];
            #pragma unroll
            for (int i = 0; i < 4; ++i)
                #pragma unroll
                for (int j = 0; j < 7; ++j)
                    acc[i][j] = fmaf(a[i], b[j], acc[i][j]);
        }
        __syncthreads();
    }

    #pragma unroll
    for (int i = 0; i < 4; ++i) {
        int r = row0 + ty * 4 + i;
        #pragma unroll
        for (int j = 0; j < 7; ++j) {
            int c = tx * 7 + j;
            if (c < NCLS) out[(size_t)r * NCLS + c] = acc[i][j] + fb[c];
        }
    }
}

// ---------------------------------------------------------------------------
extern "C" void kernel_launch(void* const* d_in, const int* in_sizes, int n_in,
                              void* d_out, int out_size)
{
    const float* x  = (const float*)d_in[0];  // time_series [16384, 2048]
    const float* w  = (const float*)d_in[1];  // w_weight    [2048, 2048]
    const float* wb = (const float*)d_in[2];  // w_bias      [2048]
    const float* fw = (const float*)d_in[3];  // fc_weight   [100, 2048]
    const float* fb = (const float*)d_in[4];  // fc_bias     [100]
    float* out = (float*)d_out;               // [16384, 100]

    dim3 g1(NIN / 128, NROWS / 128);          // 16 x 128
    gemm1_kernel<<<g1, 256>>>(x, w, wb);
    warp_rows_kernel<<<NROWS, 256>>>(x);
    gemm2_kernel<<<NROWS / 64, 256>>>(fw, fb, out);
}

// round 3
// speedup vs baseline: 1.0434x; 1.0434x over previous
#include <cuda_runtime.h>
#include <math.h>
#include <stdint.h>

#define NROWS 16384
#define NIN   2048
#define NCLS  100

// Scratch: holds z after GEMM1, overwritten row-by-row with warped values.
static __device__ float g_buf[(size_t)NROWS * NIN];

// ---------------------------------------------------------------------------
// GEMM1: C[m,n] = sum_k A[m,k] * W[n,k] + bias[n]   (TN, both K-major)
// Tile 128x128x16, 256 threads, 8 rows x 4 col-pairs per thread using
// packed fma.rn.f32x2 (FFMA2, dual-rate fp32 on sm_10x).
// Double-buffered SMEM with register prefetch, one __syncthreads per stage.
// ---------------------------------------------------------------------------
__global__ void __launch_bounds__(256)
gemm1_kernel(const float* __restrict__ A, const float* __restrict__ W,
             const float* __restrict__ bias)
{
    const int K = NIN;
    __shared__ float As[2][16][132];
    __shared__ float Bs[2][16][132];

    const int tid = threadIdx.x;
    const int bm = blockIdx.y * 128;
    const int bn = blockIdx.x * 128;
    const int tx = tid & 15;
    const int ty = tid >> 4;

    // per-thread staging coords (2 float4 per array per stage)
    const int m0 = (tid + 0)   >> 2;          // 0..63
    const int m1 = (tid + 256) >> 2;          // 64..127
    const int k40 = (tid & 3) << 2;           // same for both halves

    unsigned long long acc[8][4] = {};        // 8 rows x 4 packed col-pairs

    float4 ra0, ra1, rb0, rb1;

    // prologue: load + store stage 0
    ra0 = *(const float4*)(A + (size_t)(bm + m0) * K + k40);
    ra1 = *(const float4*)(A + (size_t)(bm + m1) * K + k40);
    rb0 = *(const float4*)(W + (size_t)(bn + m0) * K + k40);
    rb1 = *(const float4*)(W + (size_t)(bn + m1) * K + k40);
    As[0][k40 + 0][m0] = ra0.x; As[0][k40 + 1][m0] = ra0.y;
    As[0][k40 + 2][m0] = ra0.z; As[0][k40 + 3][m0] = ra0.w;
    As[0][k40 + 0][m1] = ra1.x; As[0][k40 + 1][m1] = ra1.y;
    As[0][k40 + 2][m1] = ra1.z; As[0][k40 + 3][m1] = ra1.w;
    Bs[0][k40 + 0][m0] = rb0.x; Bs[0][k40 + 1][m0] = rb0.y;
    Bs[0][k40 + 2][m0] = rb0.z; Bs[0][k40 + 3][m0] = rb0.w;
    Bs[0][k40 + 0][m1] = rb1.x; Bs[0][k40 + 1][m1] = rb1.y;
    Bs[0][k40 + 2][m1] = rb1.z; Bs[0][k40 + 3][m1] = rb1.w;
    __syncthreads();

    const int NT = K / 16;  // 128 stages
    for (int t = 0; t < NT; ++t) {
        const int s = t & 1;

        if (t + 1 < NT) {
            const int k0 = (t + 1) * 16 + k40;
            ra0 = *(const float4*)(A + (size_t)(bm + m0) * K + k0);
            ra1 = *(const float4*)(A + (size_t)(bm + m1) * K + k0);
            rb0 = *(const float4*)(W + (size_t)(bn + m0) * K + k0);
            rb1 = *(const float4*)(W + (size_t)(bn + m1) * K + k0);
        }

        #pragma unroll
        for (int k = 0; k < 16; ++k) {
            float a[8];
            *(float4*)(a)     = *(const float4*)&As[s][k][ty * 4];
            *(float4*)(a + 4) = *(const float4*)&As[s][k][64 + ty * 4];
            ulonglong2 p0 = *(const ulonglong2*)&Bs[s][k][tx * 4];
            ulonglong2 p1 = *(const ulonglong2*)&Bs[s][k][64 + tx * 4];
            unsigned long long bb[4] = {p0.x, p0.y, p1.x, p1.y};
            #pragma unroll
            for (int i = 0; i < 8; ++i) {
                unsigned long long a2;
                asm("mov.b64 %0, {%1, %1};" : "=l"(a2) : "f"(a[i]));
                #pragma unroll
                for (int j = 0; j < 4; ++j)
                    asm("fma.rn.f32x2 %0, %1, %2, %0;"
                        : "+l"(acc[i][j]) : "l"(a2), "l"(bb[j]));
            }
        }

        if (t + 1 < NT) {
            const int ns = s ^ 1;
            As[ns][k40 + 0][m0] = ra0.x; As[ns][k40 + 1][m0] = ra0.y;
            As[ns][k40 + 2][m0] = ra0.z; As[ns][k40 + 3][m0] = ra0.w;
            As[ns][k40 + 0][m1] = ra1.x; As[ns][k40 + 1][m1] = ra1.y;
            As[ns][k40 + 2][m1] = ra1.z; As[ns][k40 + 3][m1] = ra1.w;
            Bs[ns][k40 + 0][m0] = rb0.x; Bs[ns][k40 + 1][m0] = rb0.y;
            Bs[ns][k40 + 2][m0] = rb0.z; Bs[ns][k40 + 3][m0] = rb0.w;
            Bs[ns][k40 + 0][m1] = rb1.x; Bs[ns][k40 + 1][m1] = rb1.y;
            Bs[ns][k40 + 2][m1] = rb1.z; Bs[ns][k40 + 3][m1] = rb1.w;
            __syncthreads();
        }
    }

    // Epilogue: unpack pairs, add bias, store.
    #pragma unroll
    for (int ri = 0; ri < 2; ++ri) {
        #pragma unroll
        for (int i = 0; i < 4; ++i) {
            const int ii = ri * 4 + i;
            const int m = bm + ri * 64 + ty * 4 + i;
            #pragma unroll
            for (int cj = 0; cj < 2; ++cj) {
                const int n = bn + cj * 64 + tx * 4;
                unsigned long long q0 = acc[ii][cj * 2 + 0];
                unsigned long long q1 = acc[ii][cj * 2 + 1];
                float4 v;
                v.x = __uint_as_float((uint32_t)q0)         + bias[n + 0];
                v.y = __uint_as_float((uint32_t)(q0 >> 32)) + bias[n + 1];
                v.z = __uint_as_float((uint32_t)q1)         + bias[n + 2];
                v.w = __uint_as_float((uint32_t)(q1 >> 32)) + bias[n + 3];
                *(float4*)(g_buf + (size_t)m * NIN + n) = v;
            }
        }
    }
}

// ---------------------------------------------------------------------------
// Row-wise: softmax -> fp64 cumsum -> interp on uniform knot grid.
// ---------------------------------------------------------------------------
__global__ void __launch_bounds__(256)
warp_rows_kernel(const float* __restrict__ X)
{
    __shared__ float  sx[NIN];
    __shared__ float  sz[NIN];
    __shared__ float  wred[8];
    __shared__ double wtot[8];

    const int row  = blockIdx.x;
    const int t    = threadIdx.x;
    const int lane = t & 31;
    const int wid  = t >> 5;
    const float* xr = X + (size_t)row * NIN;
    float* zr = g_buf + (size_t)row * NIN;

    for (int i = t; i < NIN; i += 256) { sx[i] = xr[i]; sz[i] = zr[i]; }
    __syncthreads();

    float mx = -INFINITY;
    for (int i = t; i < NIN; i += 256) mx = fmaxf(mx, sz[i]);
    #pragma unroll
    for (int d = 16; d; d >>= 1) mx = fmaxf(mx, __shfl_xor_sync(0xffffffffu, mx, d));
    if (lane == 0) wred[wid] = mx;
    __syncthreads();
    float bmax = wred[0];
    #pragma unroll
    for (int i = 1; i < 8; ++i) bmax = fmaxf(bmax, wred[i]);

    const int base = t * 8;
    double csum[8];
    double run = 0.0;
    #pragma unroll
    for (int i = 0; i < 8; ++i) {
        float e = expf(sz[base + i] - bmax);
        run += (double)e;
        csum[i] = run;
    }

    double v = run;
    #pragma unroll
    for (int d = 1; d < 32; d <<= 1) {
        double u = __shfl_up_sync(0xffffffffu, v, d);
        if (lane >= d) v += u;
    }
    if (lane == 31) wtot[wid] = v;
    __syncthreads();
    double total = 0.0, woff = 0.0;
    #pragma unroll
    for (int i = 0; i < 8; ++i) {         // fixed order: identical on all threads
        if (i == wid) woff = total;
        total += wtot[i];
    }
    const double toff = woff + (v - run);
    const double inv  = 1.0 / total;

    #pragma unroll
    for (int i = 0; i < 8; ++i) {
        double pos = (toff + csum[i]) * inv * (double)(NIN - 1);
        pos = fmin(fmax(pos, 0.0), (double)(NIN - 1));
        int idx = (int)pos;
        if (idx > NIN - 2) idx = NIN - 2;
        float w  = (float)(pos - (double)idx);
        float y0 = sx[idx], y1 = sx[idx + 1];
        zr[base + i] = fmaf(w, y1 - y0, y0);
    }
}

// ---------------------------------------------------------------------------
// GEMM2: out[r,c] = sum_k warped[r,k] * F[c,k] + fb[c]
// Tile 64 rows x 112 cols x 32 K; 256 threads, 4x7/thread.
// B loaded with float4 LDG (K-contiguous) + scatter STS.
// ---------------------------------------------------------------------------
__global__ void __launch_bounds__(256)
gemm2_kernel(const float* __restrict__ F, const float* __restrict__ fb,
             float* __restrict__ out)
{
    __shared__ float As[32][68];
    __shared__ float Bs[32][113];

    const int tid  = threadIdx.x;
    const int row0 = blockIdx.x * 64;
    const int tx   = tid & 15;
    const int ty   = tid >> 4;

    float acc[4][7] = {};

    for (int k0 = 0; k0 < NIN; k0 += 32) {
        #pragma unroll
        for (int i = 0; i < 2; ++i) {
            int f  = tid + i * 256;      // 512 float4 = 64x32 A tile
            int r  = f >> 3;
            int k4 = (f & 7) << 2;
            float4 v = *(const float4*)(g_buf + (size_t)(row0 + r) * NIN + k0 + k4);
            As[k4 + 0][r] = v.x; As[k4 + 1][r] = v.y;
            As[k4 + 2][r] = v.z; As[k4 + 3][r] = v.w;
        }
        // B tile: 112 cols x 32 k = 896 float4 loads (vectorized along K)
        #pragma unroll
        for (int i = 0; i < 4; ++i) {
            int f = tid + i * 256;       // float4 index: c = f>>3, k4 = (f&7)*4
            if (f < 896) {
                int c  = f >> 3;
                int k4 = (f & 7) << 2;
                float4 v = (c < NCLS)
                    ? *(const float4*)(F + (size_t)c * NIN + k0 + k4)
                    : make_float4(0.f, 0.f, 0.f, 0.f);
                Bs[k4 + 0][c] = v.x; Bs[k4 + 1][c] = v.y;
                Bs[k4 + 2][c] = v.z; Bs[k4 + 3][c] = v.w;
            }
        }
        __syncthreads();

        #pragma unroll
        for (int k = 0; k < 32; ++k) {
            float a[4];
            *(float4*)a = *(const float4*)&As[k][ty * 4];
            float b[7];
            #pragma unroll
            for (int j = 0; j < 7; ++j) b[j] = Bs[k][tx * 7 + j];
            #pragma unroll
            for (int i = 0; i < 4; ++i)
                #pragma unroll
                for (int j = 0; j < 7; ++j)
                    acc[i][j] = fmaf(a[i], b[j], acc[i][j]);
        }
        __syncthreads();
    }

    #pragma unroll
    for (int i = 0; i < 4; ++i) {
        int r = row0 + ty * 4 + i;
        #pragma unroll
        for (int j = 0; j < 7; ++j) {
            int c = tx * 7 + j;
            if (c < NCLS) out[(size_t)r * NCLS + c] = acc[i][j] + fb[c];
        }
    }
}

// ---------------------------------------------------------------------------
extern "C" void kernel_launch(void* const* d_in, const int* in_sizes, int n_in,
                              void* d_out, int out_size)
{
    const float* x  = (const float*)d_in[0];  // time_series [16384, 2048]
    const float* w  = (const float*)d_in[1];  // w_weight    [2048, 2048]
    const float* wb = (const float*)d_in[2];  // w_bias      [2048]
    const float* fw = (const float*)d_in[3];  // fc_weight   [100, 2048]
    const float* fb = (const float*)d_in[4];  // fc_bias     [100]
    float* out = (float*)d_out;               // [16384, 100]

    dim3 g1(NIN / 128, NROWS / 128);          // 16 x 128
    gemm1_kernel<<<g1, 256>>>(x, w, wb);
    warp_rows_kernel<<<NROWS, 256>>>(x);
    gemm2_kernel<<<NROWS / 64, 256>>>(fw, fb, out);
}

// round 4
// speedup vs baseline: 1.1936x; 1.1440x over previous
#include <cuda_runtime.h>
#include <math.h>
#include <stdint.h>

#define NROWS 16384
#define NIN   2048
#define NCLS  100

// Scratch: holds z after GEMM1, overwritten row-by-row with warped values.
static __device__ float g_buf[(size_t)NROWS * NIN];

// ---------------------------------------------------------------------------
// GEMM1 on tensor cores (mma.sync m16n8k8 tf32, 3-term split precision).
// C[m,n] = sum_k A[m,k] * W[n,k] + bias[n]   (TN, both K-major)
// Tile 128x128x16, 256 threads; warps 4(m) x 2(n) -> warp tile 32x64.
// SMEM: hi/lo tf32 panels, [row][20] padded, double-buffered (80 KB dynamic).
// ---------------------------------------------------------------------------
#define BK     16
#define LDP    20                       // row stride in floats (pad 4)
#define PANEL  (128 * LDP)              // floats per panel per stage

__device__ __forceinline__ void tf32_split4(float4 v, uint4& hi, uint4& lo) {
    float r;
    asm("cvt.rna.tf32.f32 %0, %1;" : "=r"(hi.x) : "f"(v.x));
    r = v.x - __uint_as_float(hi.x);
    asm("cvt.rna.tf32.f32 %0, %1;" : "=r"(lo.x) : "f"(r));
    asm("cvt.rna.tf32.f32 %0, %1;" : "=r"(hi.y) : "f"(v.y));
    r = v.y - __uint_as_float(hi.y);
    asm("cvt.rna.tf32.f32 %0, %1;" : "=r"(lo.y) : "f"(r));
    asm("cvt.rna.tf32.f32 %0, %1;" : "=r"(hi.z) : "f"(v.z));
    r = v.z - __uint_as_float(hi.z);
    asm("cvt.rna.tf32.f32 %0, %1;" : "=r"(lo.z) : "f"(r));
    asm("cvt.rna.tf32.f32 %0, %1;" : "=r"(hi.w) : "f"(v.w));
    r = v.w - __uint_as_float(hi.w);
    asm("cvt.rna.tf32.f32 %0, %1;" : "=r"(lo.w) : "f"(r));
}

#define MMA_TF32(d, a, b0, b1)                                              \
    asm volatile("mma.sync.aligned.m16n8k8.row.col.f32.tf32.tf32.f32 "      \
                 "{%0,%1,%2,%3}, {%4,%5,%6,%7}, {%8,%9}, {%0,%1,%2,%3};"    \
                 : "+f"((d)[0]), "+f"((d)[1]), "+f"((d)[2]), "+f"((d)[3])   \
                 : "r"((a)[0]), "r"((a)[1]), "r"((a)[2]), "r"((a)[3]),      \
                   "r"(b0), "r"(b1))

__global__ void __launch_bounds__(256)
gemm1_mma_kernel(const float* __restrict__ A, const float* __restrict__ W,
                 const float* __restrict__ bias)
{
    extern __shared__ float sm[];
    // panels: [0]=Ah, [1]=Al, [2]=Bh, [3]=Bl; each has 2 stages
    float* Ah = sm;
    float* Al = sm + 2 * PANEL;
    float* Bh = sm + 4 * PANEL;
    float* Bl = sm + 6 * PANEL;

    const int K = NIN;
    const int tid  = threadIdx.x;
    const int lane = tid & 31;
    const int wid  = tid >> 5;
    const int bm = blockIdx.y * 128;
    const int bn = blockIdx.x * 128;

    const int wm = (wid & 3) * 32;      // warp m-offset in tile
    const int wn = (wid >> 2) * 64;     // warp n-offset in tile
    const int r0 = lane >> 2;           // 0..7
    const int c0 = lane & 3;            // 0..3

    // staging coords: f = tid + i*256 -> m = f>>2 (0..127), k0 = (f&3)*4
    const int sm0 = tid >> 2;           // i=0 rows 0..63
    const int sm1 = sm0 + 64;           // i=1 rows 64..127
    const int sk0 = (tid & 3) << 2;

    float acc[2][8][4] = {};

    float4 ra0, ra1, rw0, rw1;

    // ---- prologue: stage 0
    ra0 = *(const float4*)(A + (size_t)(bm + sm0) * K + sk0);
    ra1 = *(const float4*)(A + (size_t)(bm + sm1) * K + sk0);
    rw0 = *(const float4*)(W + (size_t)(bn + sm0) * K + sk0);
    rw1 = *(const float4*)(W + (size_t)(bn + sm1) * K + sk0);
    {
        uint4 h, l;
        tf32_split4(ra0, h, l);
        *(uint4*)(Ah + sm0 * LDP + sk0) = h; *(uint4*)(Al + sm0 * LDP + sk0) = l;
        tf32_split4(ra1, h, l);
        *(uint4*)(Ah + sm1 * LDP + sk0) = h; *(uint4*)(Al + sm1 * LDP + sk0) = l;
        tf32_split4(rw0, h, l);
        *(uint4*)(Bh + sm0 * LDP + sk0) = h; *(uint4*)(Bl + sm0 * LDP + sk0) = l;
        tf32_split4(rw1, h, l);
        *(uint4*)(Bh + sm1 * LDP + sk0) = h; *(uint4*)(Bl + sm1 * LDP + sk0) = l;
    }
    __syncthreads();

    const int NT = K / BK;              // 128 stages
    for (int t = 0; t < NT; ++t) {
        const int s = t & 1;
        const float* ah = Ah + s * PANEL;
        const float* al = Al + s * PANEL;
        const float* bh = Bh + s * PANEL;
        const float* bl = Bl + s * PANEL;

        if (t + 1 < NT) {
            const int kg = (t + 1) * BK + sk0;
            ra0 = *(const float4*)(A + (size_t)(bm + sm0) * K + kg);
            ra1 = *(const float4*)(A + (size_t)(bm + sm1) * K + kg);
            rw0 = *(const float4*)(W + (size_t)(bn + sm0) * K + kg);
            rw1 = *(const float4*)(W + (size_t)(bn + sm1) * K + kg);
        }

        #pragma unroll
        for (int kk = 0; kk < BK; kk += 8) {
            uint32_t afh[2][4], afl[2][4];
            #pragma unroll
            for (int mt = 0; mt < 2; ++mt) {
                const int rb = (wm + mt * 16 + r0) * LDP + kk + c0;
                afh[mt][0] = __float_as_uint(ah[rb]);
                afh[mt][1] = __float_as_uint(ah[rb + 8 * LDP]);
                afh[mt][2] = __float_as_uint(ah[rb + 4]);
                afh[mt][3] = __float_as_uint(ah[rb + 8 * LDP + 4]);
                afl[mt][0] = __float_as_uint(al[rb]);
                afl[mt][1] = __float_as_uint(al[rb + 8 * LDP]);
                afl[mt][2] = __float_as_uint(al[rb + 4]);
                afl[mt][3] = __float_as_uint(al[rb + 8 * LDP + 4]);
            }
            #pragma unroll
            for (int nt = 0; nt < 8; ++nt) {
                const int nb = (wn + nt * 8 + r0) * LDP + kk + c0;
                const uint32_t bh0 = __float_as_uint(bh[nb]);
                const uint32_t bh1 = __float_as_uint(bh[nb + 4]);
                const uint32_t bl0 = __float_as_uint(bl[nb]);
                const uint32_t bl1 = __float_as_uint(bl[nb + 4]);
                #pragma unroll
                for (int mt = 0; mt < 2; ++mt) {
                    MMA_TF32(acc[mt][nt], afh[mt], bh0, bh1);
                    MMA_TF32(acc[mt][nt], afl[mt], bh0, bh1);
                    MMA_TF32(acc[mt][nt], afh[mt], bl0, bl1);
                }
            }
        }

        if (t + 1 < NT) {
            const int ns = s ^ 1;
            float* nAh = Ah + ns * PANEL; float* nAl = Al + ns * PANEL;
            float* nBh = Bh + ns * PANEL; float* nBl = Bl + ns * PANEL;
            uint4 h, l;
            tf32_split4(ra0, h, l);
            *(uint4*)(nAh + sm0 * LDP + sk0) = h; *(uint4*)(nAl + sm0 * LDP + sk0) = l;
            tf32_split4(ra1, h, l);
            *(uint4*)(nAh + sm1 * LDP + sk0) = h; *(uint4*)(nAl + sm1 * LDP + sk0) = l;
            tf32_split4(rw0, h, l);
            *(uint4*)(nBh + sm0 * LDP + sk0) = h; *(uint4*)(nBl + sm0 * LDP + sk0) = l;
            tf32_split4(rw1, h, l);
            *(uint4*)(nBh + sm1 * LDP + sk0) = h; *(uint4*)(nBl + sm1 * LDP + sk0) = l;
            __syncthreads();
        }
    }

    // ---- epilogue: D rows (r0, r0+8), cols c0*2 (+1) per m16n8 tile
    #pragma unroll
    for (int mt = 0; mt < 2; ++mt) {
        const int m_lo = bm + wm + mt * 16 + r0;
        #pragma unroll
        for (int nt = 0; nt < 8; ++nt) {
            const int n = bn + wn + nt * 8 + c0 * 2;
            const float2 bv = *(const float2*)(bias + n);
            float2 v0, v1;
            v0.x = acc[mt][nt][0] + bv.x;
            v0.y = acc[mt][nt][1] + bv.y;
            v1.x = acc[mt][nt][2] + bv.x;
            v1.y = acc[mt][nt][3] + bv.y;
            *(float2*)(g_buf + (size_t)m_lo * NIN + n)       = v0;
            *(float2*)(g_buf + (size_t)(m_lo + 8) * NIN + n) = v1;
        }
    }
}

#define GEMM1_SMEM (8 * PANEL * 4)      // 81920 bytes

// ---------------------------------------------------------------------------
// Row-wise: softmax -> fp64 cumsum -> interp on uniform knot grid.
// ---------------------------------------------------------------------------
__global__ void __launch_bounds__(256)
warp_rows_kernel(const float* __restrict__ X)
{
    __shared__ float  sx[NIN];
    __shared__ float  sz[NIN];
    __shared__ float  wred[8];
    __shared__ double wtot[8];

    const int row  = blockIdx.x;
    const int t    = threadIdx.x;
    const int lane = t & 31;
    const int wid  = t >> 5;
    const float* xr = X + (size_t)row * NIN;
    float* zr = g_buf + (size_t)row * NIN;

    for (int i = t; i < NIN; i += 256) { sx[i] = xr[i]; sz[i] = zr[i]; }
    __syncthreads();

    float mx = -INFINITY;
    for (int i = t; i < NIN; i += 256) mx = fmaxf(mx, sz[i]);
    #pragma unroll
    for (int d = 16; d; d >>= 1) mx = fmaxf(mx, __shfl_xor_sync(0xffffffffu, mx, d));
    if (lane == 0) wred[wid] = mx;
    __syncthreads();
    float bmax = wred[0];
    #pragma unroll
    for (int i = 1; i < 8; ++i) bmax = fmaxf(bmax, wred[i]);

    const int base = t * 8;
    double csum[8];
    double run = 0.0;
    #pragma unroll
    for (int i = 0; i < 8; ++i) {
        float e = expf(sz[base + i] - bmax);
        run += (double)e;
        csum[i] = run;
    }

    double v = run;
    #pragma unroll
    for (int d = 1; d < 32; d <<= 1) {
        double u = __shfl_up_sync(0xffffffffu, v, d);
        if (lane >= d) v += u;
    }
    if (lane == 31) wtot[wid] = v;
    __syncthreads();
    double total = 0.0, woff = 0.0;
    #pragma unroll
    for (int i = 0; i < 8; ++i) {         // fixed order: identical on all threads
        if (i == wid) woff = total;
        total += wtot[i];
    }
    const double toff = woff + (v - run);
    const double inv  = 1.0 / total;

    #pragma unroll
    for (int i = 0; i < 8; ++i) {
        double pos = (toff + csum[i]) * inv * (double)(NIN - 1);
        pos = fmin(fmax(pos, 0.0), (double)(NIN - 1));
        int idx = (int)pos;
        if (idx > NIN - 2) idx = NIN - 2;
        float w  = (float)(pos - (double)idx);
        float y0 = sx[idx], y1 = sx[idx + 1];
        zr[base + i] = fmaf(w, y1 - y0, y0);
    }
}

// ---------------------------------------------------------------------------
// GEMM2: out[r,c] = sum_k warped[r,k] * F[c,k] + fb[c]
// Tile 64 rows x 112 cols x 32 K; 256 threads, 4x7/thread.
// ---------------------------------------------------------------------------
__global__ void __launch_bounds__(256)
gemm2_kernel(const float* __restrict__ F, const float* __restrict__ fb,
             float* __restrict__ out)
{
    __shared__ float As[32][68];
    __shared__ float Bs[32][113];

    const int tid  = threadIdx.x;
    const int row0 = blockIdx.x * 64;
    const int tx   = tid & 15;
    const int ty   = tid >> 4;

    float acc[4][7] = {};

    for (int k0 = 0; k0 < NIN; k0 += 32) {
        #pragma unroll
        for (int i = 0; i < 2; ++i) {
            int f  = tid + i * 256;
            int r  = f >> 3;
            int k4 = (f & 7) << 2;
            float4 v = *(const float4*)(g_buf + (size_t)(row0 + r) * NIN + k0 + k4);
            As[k4 + 0][r] = v.x; As[k4 + 1][r] = v.y;
            As[k4 + 2][r] = v.z; As[k4 + 3][r] = v.w;
        }
        #pragma unroll
        for (int i = 0; i < 4; ++i) {
            int f = tid + i * 256;
            if (f < 896) {
                int c  = f >> 3;
                int k4 = (f & 7) << 2;
                float4 v = (c < NCLS)
                    ? *(const float4*)(F + (size_t)c * NIN + k0 + k4)
                    : make_float4(0.f, 0.f, 0.f, 0.f);
                Bs[k4 + 0][c] = v.x; Bs[k4 + 1][c] = v.y;
                Bs[k4 + 2][c] = v.z; Bs[k4 + 3][c] = v.w;
            }
        }
        __syncthreads();

        #pragma unroll
        for (int k = 0; k < 32; ++k) {
            float a[4];
            *(float4*)a = *(const float4*)&As[k][ty * 4];
            float b[7];
            #pragma unroll
            for (int j = 0; j < 7; ++j) b[j] = Bs[k][tx * 7 + j];
            #pragma unroll
            for (int i = 0; i < 4; ++i)
                #pragma unroll
                for (int j = 0; j < 7; ++j)
                    acc[i][j] = fmaf(a[i], b[j], acc[i][j]);
        }
        __syncthreads();
    }

    #pragma unroll
    for (int i = 0; i < 4; ++i) {
        int r = row0 + ty * 4 + i;
        #pragma unroll
        for (int j = 0; j < 7; ++j) {
            int c = tx * 7 + j;
            if (c < NCLS) out[(size_t)r * NCLS + c] = acc[i][j] + fb[c];
        }
    }
}

// ---------------------------------------------------------------------------
extern "C" void kernel_launch(void* const* d_in, const int* in_sizes, int n_in,
                              void* d_out, int out_size)
{
    const float* x  = (const float*)d_in[0];  // time_series [16384, 2048]
    const float* w  = (const float*)d_in[1];  // w_weight    [2048, 2048]
    const float* wb = (const float*)d_in[2];  // w_bias      [2048]
    const float* fw = (const float*)d_in[3];  // fc_weight   [100, 2048]
    const float* fb = (const float*)d_in[4];  // fc_bias     [100]
    float* out = (float*)d_out;               // [16384, 100]

    cudaFuncSetAttribute(gemm1_mma_kernel,
                         cudaFuncAttributeMaxDynamicSharedMemorySize, GEMM1_SMEM);

    dim3 g1(NIN / 128, NROWS / 128);          // 16 x 128
    gemm1_mma_kernel<<<g1, 256, GEMM1_SMEM>>>(x, w, wb);
    warp_rows_kernel<<<NROWS, 256>>>(x);
    gemm2_kernel<<<NROWS / 64, 256>>>(fw, fb, out);
}

// round 5
// speedup vs baseline: 1.3003x; 1.0894x over previous
#include <cuda_runtime.h>
#include <math.h>
#include <stdint.h>

#define NROWS 16384
#define NIN   2048
#define NCLS  100

// Scratch
static __device__ float g_buf[(size_t)NROWS * NIN];        // z, then warped
static __device__ float g_apre[(size_t)NROWS * NIN * 2];   // A hi/lo, frag layout
static __device__ float g_wpre[(size_t)NIN * NIN * 2];     // W hi/lo, frag layout

// ---------------------------------------------------------------------------
// helpers
// ---------------------------------------------------------------------------
__device__ __forceinline__ uint32_t smem_u32(const void* p) {
    uint32_t a;
    asm("{ .reg .u64 t; cvta.to.shared.u64 t, %1; cvt.u32.u64 %0, t; }" : "=r"(a) : "l"(p));
    return a;
}

__device__ __forceinline__ void tf32_split1(float a, uint32_t& hi, uint32_t& lo) {
    asm("cvt.rna.tf32.f32 %0, %1;" : "=r"(hi) : "f"(a));
    float r = a - __uint_as_float(hi);
    asm("cvt.rna.tf32.f32 %0, %1;" : "=r"(lo) : "f"(r));
}
__device__ __forceinline__ void tf32_split4(float4 v, uint4& hi, uint4& lo) {
    tf32_split1(v.x, hi.x, lo.x);
    tf32_split1(v.y, hi.y, lo.y);
    tf32_split1(v.z, hi.z, lo.z);
    tf32_split1(v.w, hi.w, lo.w);
}

#define MMA_TF32(d, a, b0, b1)                                              \
    asm volatile("mma.sync.aligned.m16n8k8.row.col.f32.tf32.tf32.f32 "      \
                 "{%0,%1,%2,%3}, {%4,%5,%6,%7}, {%8,%9}, {%0,%1,%2,%3};"    \
                 : "+f"((d)[0]), "+f"((d)[1]), "+f"((d)[2]), "+f"((d)[3])   \
                 : "r"((a)[0]), "r"((a)[1]), "r"((a)[2]), "r"((a)[3]),      \
                   "r"(b0), "r"(b1))

#define CP_ASYNC16(dst, src) \
    asm volatile("cp.async.cg.shared.global [%0], [%1], 16;" :: "r"(dst), "l"(src) : "memory")
#define CP_COMMIT()  asm volatile("cp.async.commit_group;" ::: "memory")
#define CP_WAIT(n)   asm volatile("cp.async.wait_group %0;" :: "n"(n) : "memory")

// ---------------------------------------------------------------------------
// Prep A: split time_series into hi/lo tf32, fragment-permuted blocks.
// Block (m_tile, ks) = 4096 floats at ((m_tile*128 + ks)*4096):
//   [mi(8)][ki(2)] -> 256 floats: hi[lane(32)][4] then lo[lane(32)][4]
// Fragment of lane l for (m16 mi, k8 ki): elements
//   A[gm][gk], A[gm+8][gk], A[gm][gk+4], A[gm+8][gk+4],
//   gm = m_tile*128 + mi*16 + (l>>2), gk = ks*16 + ki*8 + (l&3).
// ---------------------------------------------------------------------------
__global__ void __launch_bounds__(256) prep_a_kernel(const float* __restrict__ A)
{
    const uint32_t u = blockIdx.x * 256 + threadIdx.x;
    const int lane = u & 31;
    const int ki   = (u >> 5) & 1;
    const int mi   = (u >> 6) & 7;
    const int ks   = (u >> 9) & 127;
    const int mt   = u >> 16;

    const int gm = mt * 128 + mi * 16 + (lane >> 2);
    const int gk = ks * 16 + ki * 8 + (lane & 3);
    const float* a = A + (size_t)gm * NIN + gk;

    float4 v;
    v.x = a[0];
    v.y = a[(size_t)8 * NIN];
    v.z = a[4];
    v.w = a[(size_t)8 * NIN + 4];
    uint4 h, l;
    tf32_split4(v, h, l);

    float* dst = g_apre + ((size_t)mt * 128 + ks) * 4096 + (mi * 2 + ki) * 256 + lane * 4;
    *(uint4*)dst         = h;
    *(uint4*)(dst + 128) = l;
}

// ---------------------------------------------------------------------------
// Prep W: block (n_tile, ks) = 4096 floats at ((n_tile*128 + ks)*4096):
//   [ni(16)][ki(2)] -> 128 floats: [lane(32)][{bh0, bh1, bl0, bl1}]
// b0 = W[gn][gk], b1 = W[gn][gk+4], gn = n_tile*128 + ni*8 + (l>>2),
// gk = ks*16 + ki*8 + (l&3).
// ---------------------------------------------------------------------------
__global__ void __launch_bounds__(256) prep_w_kernel(const float* __restrict__ W)
{
    const uint32_t u = blockIdx.x * 256 + threadIdx.x;
    const int lane = u & 31;
    const int ki   = (u >> 5) & 1;
    const int ni   = (u >> 6) & 15;
    const int ks   = (u >> 10) & 127;
    const int nt   = u >> 17;

    const int gn = nt * 128 + ni * 8 + (lane >> 2);
    const int gk = ks * 16 + ki * 8 + (lane & 3);
    const float* b = W + (size_t)gn * NIN + gk;

    uint4 o;
    uint32_t bl0, bl1;
    tf32_split1(b[0], o.x, bl0);
    tf32_split1(b[4], o.y, bl1);
    o.z = bl0; o.w = bl1;

    float* dst = g_wpre + ((size_t)nt * 128 + ks) * 4096 + (ni * 2 + ki) * 128 + lane * 4;
    *(uint4*)dst = o;
}

// ---------------------------------------------------------------------------
// GEMM1 on tensor cores, fragment-layout staging via cp.async, 3-stage pipe.
// Tile 128x128x16, 256 threads; warps 4(m) x 2(n), warp tile 32x64.
// SMEM per stage: A block 16 KB + B block 16 KB = 32 KB; 3 stages = 96 KB.
// ---------------------------------------------------------------------------
#define NT_STAGES (NIN / 16)            // 128
#define STG_BYTES 32768
#define GEMM1_SMEM (3 * STG_BYTES)

__global__ void __launch_bounds__(256, 2)
gemm1_mma_kernel(const float* __restrict__ bias)
{
    extern __shared__ float smf[];
    const uint32_t smb = smem_u32(smf);
    const int tid  = threadIdx.x;
    const int lane = tid & 31;
    const int wid  = tid >> 5;

    const float* gA = g_apre + (size_t)blockIdx.y * 128 * 4096;
    const float* gB = g_wpre + (size_t)blockIdx.x * 128 * 4096;

    const int wmi = (wid & 3) * 2;      // m16 block base for this warp
    const int wni = (wid >> 2) * 8;     // n8 block base

    float acc[2][8][4] = {};

    // staging: 8 cp.async x 16B per thread per stage (A 4 + B 4)
    #define ISSUE(t, s) do {                                                   \
        uint32_t dA = smb + (s) * STG_BYTES;                                   \
        const float* srcA = gA + (size_t)(t) * 4096;                           \
        const float* srcB = gB + (size_t)(t) * 4096;                           \
        _Pragma("unroll")                                                      \
        for (int j = 0; j < 4; ++j) {                                          \
            CP_ASYNC16(dA + (tid + j * 256) * 16, srcA + (tid + j * 256) * 4); \
            CP_ASYNC16(dA + 16384 + (tid + j * 256) * 16,                      \
                       srcB + (tid + j * 256) * 4);                            \
        }                                                                      \
        CP_COMMIT();                                                           \
    } while (0)

    ISSUE(0, 0);
    ISSUE(1, 1);

    for (int t = 0; t < NT_STAGES; ++t) {
        const int s = t % 3;
        if (t == NT_STAGES - 1) { CP_WAIT(0); } else { CP_WAIT(1); }
        __syncthreads();
        if (t + 2 < NT_STAGES) ISSUE(t + 2, (t + 2) % 3);

        const float* sA = smf + s * 8192;
        const float* sB = sA + 4096;

        #pragma unroll
        for (int kk = 0; kk < 2; ++kk) {
            uint32_t afh[2][4], afl[2][4];
            #pragma unroll
            for (int mt = 0; mt < 2; ++mt) {
                const float* pa = sA + ((wmi + mt) * 2 + kk) * 256 + lane * 4;
                float4 h = *(const float4*)pa;
                float4 l = *(const float4*)(pa + 128);
                afh[mt][0] = __float_as_uint(h.x); afh[mt][1] = __float_as_uint(h.y);
                afh[mt][2] = __float_as_uint(h.z); afh[mt][3] = __float_as_uint(h.w);
                afl[mt][0] = __float_as_uint(l.x); afl[mt][1] = __float_as_uint(l.y);
                afl[mt][2] = __float_as_uint(l.z); afl[mt][3] = __float_as_uint(l.w);
            }
            #pragma unroll
            for (int nt = 0; nt < 8; ++nt) {
                const float4 bv = *(const float4*)(sB + ((wni + nt) * 2 + kk) * 128 + lane * 4);
                const uint32_t bh0 = __float_as_uint(bv.x);
                const uint32_t bh1 = __float_as_uint(bv.y);
                const uint32_t bl0 = __float_as_uint(bv.z);
                const uint32_t bl1 = __float_as_uint(bv.w);
                #pragma unroll
                for (int mt = 0; mt < 2; ++mt) {
                    MMA_TF32(acc[mt][nt], afh[mt], bh0, bh1);
                    MMA_TF32(acc[mt][nt], afl[mt], bh0, bh1);
                    MMA_TF32(acc[mt][nt], afh[mt], bl0, bl1);
                }
            }
        }
    }
    #undef ISSUE

    // epilogue
    const int bm = blockIdx.y * 128;
    const int bn = blockIdx.x * 128;
    const int r0 = lane >> 2;
    const int c0 = lane & 3;
    #pragma unroll
    for (int mt = 0; mt < 2; ++mt) {
        const int m_lo = bm + (wid & 3) * 32 + mt * 16 + r0;
        #pragma unroll
        for (int nt = 0; nt < 8; ++nt) {
            const int n = bn + (wid >> 2) * 64 + nt * 8 + c0 * 2;
            const float2 bv = *(const float2*)(bias + n);
            float2 v0, v1;
            v0.x = acc[mt][nt][0] + bv.x;
            v0.y = acc[mt][nt][1] + bv.y;
            v1.x = acc[mt][nt][2] + bv.x;
            v1.y = acc[mt][nt][3] + bv.y;
            *(float2*)(g_buf + (size_t)m_lo * NIN + n)       = v0;
            *(float2*)(g_buf + (size_t)(m_lo + 8) * NIN + n) = v1;
        }
    }
}

// ---------------------------------------------------------------------------
// Row-wise: softmax -> fp64 cumsum -> interp on uniform knot grid.
// ---------------------------------------------------------------------------
__global__ void __launch_bounds__(256)
warp_rows_kernel(const float* __restrict__ X)
{
    __shared__ float  sx[NIN];
    __shared__ float  sz[NIN];
    __shared__ float  wred[8];
    __shared__ double wtot[8];

    const int row  = blockIdx.x;
    const int t    = threadIdx.x;
    const int lane = t & 31;
    const int wid  = t >> 5;
    const float* xr = X + (size_t)row * NIN;
    float* zr = g_buf + (size_t)row * NIN;

    for (int i = t; i < NIN; i += 256) { sx[i] = xr[i]; sz[i] = zr[i]; }
    __syncthreads();

    float mx = -INFINITY;
    for (int i = t; i < NIN; i += 256) mx = fmaxf(mx, sz[i]);
    #pragma unroll
    for (int d = 16; d; d >>= 1) mx = fmaxf(mx, __shfl_xor_sync(0xffffffffu, mx, d));
    if (lane == 0) wred[wid] = mx;
    __syncthreads();
    float bmax = wred[0];
    #pragma unroll
    for (int i = 1; i < 8; ++i) bmax = fmaxf(bmax, wred[i]);

    const int base = t * 8;
    double csum[8];
    double run = 0.0;
    #pragma unroll
    for (int i = 0; i < 8; ++i) {
        float e = expf(sz[base + i] - bmax);
        run += (double)e;
        csum[i] = run;
    }

    double v = run;
    #pragma unroll
    for (int d = 1; d < 32; d <<= 1) {
        double u = __shfl_up_sync(0xffffffffu, v, d);
        if (lane >= d) v += u;
    }
    if (lane == 31) wtot[wid] = v;
    __syncthreads();
    double total = 0.0, woff = 0.0;
    #pragma unroll
    for (int i = 0; i < 8; ++i) {
        if (i == wid) woff = total;
        total += wtot[i];
    }
    const double toff = woff + (v - run);
    const double inv  = 1.0 / total;

    #pragma unroll
    for (int i = 0; i < 8; ++i) {
        double pos = (toff + csum[i]) * inv * (double)(NIN - 1);
        pos = fmin(fmax(pos, 0.0), (double)(NIN - 1));
        int idx = (int)pos;
        if (idx > NIN - 2) idx = NIN - 2;
        float w  = (float)(pos - (double)idx);
        float y0 = sx[idx], y1 = sx[idx + 1];
        zr[base + i] = fmaf(w, y1 - y0, y0);
    }
}

// ---------------------------------------------------------------------------
// GEMM2: out[r,c] = sum_k warped[r,k] * F[c,k] + fb[c]
// ---------------------------------------------------------------------------
__global__ void __launch_bounds__(256)
gemm2_kernel(const float* __restrict__ F, const float* __restrict__ fb,
             float* __restrict__ out)
{
    __shared__ float As[32][68];
    __shared__ float Bs[32][113];

    const int tid  = threadIdx.x;
    const int row0 = blockIdx.x * 64;
    const int tx   = tid & 15;
    const int ty   = tid >> 4;

    float acc[4][7] = {};

    for (int k0 = 0; k0 < NIN; k0 += 32) {
        #pragma unroll
        for (int i = 0; i < 2; ++i) {
            int f  = tid + i * 256;
            int r  = f >> 3;
            int k4 = (f & 7) << 2;
            float4 v = *(const float4*)(g_buf + (size_t)(row0 + r) * NIN + k0 + k4);
            As[k4 + 0][r] = v.x; As[k4 + 1][r] = v.y;
            As[k4 + 2][r] = v.z; As[k4 + 3][r] = v.w;
        }
        #pragma unroll
        for (int i = 0; i < 4; ++i) {
            int f = tid + i * 256;
            if (f < 896) {
                int c  = f >> 3;
                int k4 = (f & 7) << 2;
                float4 v = (c < NCLS)
                    ? *(const float4*)(F + (size_t)c * NIN + k0 + k4)
                    : make_float4(0.f, 0.f, 0.f, 0.f);
                Bs[k4 + 0][c] = v.x; Bs[k4 + 1][c] = v.y;
                Bs[k4 + 2][c] = v.z; Bs[k4 + 3][c] = v.w;
            }
        }
        __syncthreads();

        #pragma unroll
        for (int k = 0; k < 32; ++k) {
            float a[4];
            *(float4*)a = *(const float4*)&As[k][ty * 4];
            float b[7];
            #pragma unroll
            for (int j = 0; j < 7; ++j) b[j] = Bs[k][tx * 7 + j];
            #pragma unroll
            for (int i = 0; i < 4; ++i)
                #pragma unroll
                for (int j = 0; j < 7; ++j)
                    acc[i][j] = fmaf(a[i], b[j], acc[i][j]);
        }
        __syncthreads();
    }

    #pragma unroll
    for (int i = 0; i < 4; ++i) {
        int r = row0 + ty * 4 + i;
        #pragma unroll
        for (int j = 0; j < 7; ++j) {
            int c = tx * 7 + j;
            if (c < NCLS) out[(size_t)r * NCLS + c] = acc[i][j] + fb[c];
        }
    }
}

// ---------------------------------------------------------------------------
extern "C" void kernel_launch(void* const* d_in, const int* in_sizes, int n_in,
                              void* d_out, int out_size)
{
    const float* x  = (const float*)d_in[0];  // time_series [16384, 2048]
    const float* w  = (const float*)d_in[1];  // w_weight    [2048, 2048]
    const float* wb = (const float*)d_in[2];  // w_bias      [2048]
    const float* fw = (const float*)d_in[3];  // fc_weight   [100, 2048]
    const float* fb = (const float*)d_in[4];  // fc_bias     [100]
    float* out = (float*)d_out;               // [16384, 100]

    cudaFuncSetAttribute(gemm1_mma_kernel,
                         cudaFuncAttributeMaxDynamicSharedMemorySize, GEMM1_SMEM);

    prep_a_kernel<<<32768, 256>>>(x);         // 128*128*512 threads
    prep_w_kernel<<<8192, 256>>>(w);          // 16*128*512 threads

    dim3 g1(NIN / 128, NROWS / 128);          // 16 x 128
    gemm1_mma_kernel<<<g1, 256, GEMM1_SMEM>>>(wb);
    warp_rows_kernel<<<NROWS, 256>>>(x);
    gemm2_kernel<<<NROWS / 64, 256>>>(fw, fb, out);
}

// round 6
// speedup vs baseline: 1.9089x; 1.4680x over previous
#include <cuda_runtime.h>
#include <cuda_fp16.h>
#include <math.h>
#include <stdint.h>

#define NROWS 16384
#define NIN   2048
#define NCLS  100

// Scratch
static __device__ float  g_buf[(size_t)NROWS * NIN];          // z, then warped
static __device__ __half g_apre[(size_t)NROWS * NIN * 2];     // A hi/lo fp16 frags
static __device__ __half g_wpre[(size_t)NIN * NIN * 2];       // W hi/lo fp16 frags

// ---------------------------------------------------------------------------
// helpers
// ---------------------------------------------------------------------------
__device__ __forceinline__ uint32_t smem_u32(const void* p) {
    uint32_t a;
    asm("{ .reg .u64 t; cvta.to.shared.u64 t, %1; cvt.u32.u64 %0, t; }" : "=r"(a) : "l"(p));
    return a;
}

__device__ __forceinline__ void h_split(float x, __half& h, __half& l) {
    h = __float2half_rn(x);
    l = __float2half_rn(x - __half2float(h));
}

#define MMA_F16(d, a, b0, b1)                                               \
    asm volatile("mma.sync.aligned.m16n8k16.row.col.f32.f16.f16.f32 "       \
                 "{%0,%1,%2,%3}, {%4,%5,%6,%7}, {%8,%9}, {%0,%1,%2,%3};"    \
                 : "+f"((d)[0]), "+f"((d)[1]), "+f"((d)[2]), "+f"((d)[3])   \
                 : "r"((a).x), "r"((a).y), "r"((a).z), "r"((a).w),          \
                   "r"(b0), "r"(b1))

#define CP_ASYNC16(dst, src) \
    asm volatile("cp.async.cg.shared.global [%0], [%1], 16;" :: "r"(dst), "l"(src) : "memory")
#define CP_COMMIT()  asm volatile("cp.async.commit_group;" ::: "memory")
#define CP_WAIT(n)   asm volatile("cp.async.wait_group %0;" :: "n"(n) : "memory")

// ---------------------------------------------------------------------------
// Prep A: split x into hi/lo fp16 limbs, fragment-permuted for m16n8k16.
// Chunk (mt, ks16) = 8 KB at ((mt*128 + ks)*512 uint4):
//   [hi: mi(8) x lane(32) uint4] then [lo: same].
// Lane fragment (uint4 = {a0,a1,a2,a3} f16x2):
//   r = mt*128 + mi*16 + (lane>>2), c = ks*16 + (lane&3)*2;
//   a0 = A[r][c..c+1], a1 = A[r+8][c..c+1], a2 = A[r][c+8..c+9], a3 = A[r+8][c+8..c+9]
// ---------------------------------------------------------------------------
__global__ void __launch_bounds__(256) prep_a_kernel(const float* __restrict__ A)
{
    const uint32_t u = blockIdx.x * 256 + threadIdx.x;
    const int lane = u & 31;
    const int mi   = (u >> 5) & 7;
    const int ks   = (u >> 8) & 127;
    const int mt   = u >> 15;

    const int r = mt * 128 + mi * 16 + (lane >> 2);
    const int c = ks * 16 + (lane & 3) * 2;
    const float* a0p = A + (size_t)r * NIN + c;
    const float* a1p = a0p + (size_t)8 * NIN;

    __half h[8], l[8];
    h_split(a0p[0], h[0], l[0]);  h_split(a0p[1], h[1], l[1]);   // a0
    h_split(a1p[0], h[2], l[2]);  h_split(a1p[1], h[3], l[3]);   // a1
    h_split(a0p[8], h[4], l[4]);  h_split(a0p[9], h[5], l[5]);   // a2
    h_split(a1p[8], h[6], l[6]);  h_split(a1p[9], h[7], l[7]);   // a3

    uint4* dst = (uint4*)g_apre + ((size_t)mt * 128 + ks) * 512 + mi * 32 + lane;
    __half2* dh = (__half2*)dst;
    dh[0] = __halves2half2(h[0], h[1]); dh[1] = __halves2half2(h[2], h[3]);
    dh[2] = __halves2half2(h[4], h[5]); dh[3] = __halves2half2(h[6], h[7]);
    __half2* dl = (__half2*)(dst + 256);
    dl[0] = __halves2half2(l[0], l[1]); dl[1] = __halves2half2(l[2], l[3]);
    dl[2] = __halves2half2(l[4], l[5]); dl[3] = __halves2half2(l[6], l[7]);
}

// ---------------------------------------------------------------------------
// Prep W: chunk (nt, ks16) = 8 KB at ((nt*128 + ks)*512 uint4): [ni(16) x lane(32)].
// Lane uint4 = {bh0, bh1, bl0, bl1}:
//   n = nt*128 + ni*8 + (lane>>2), k = ks*16 + (lane&3)*2;
//   b0 = W[n][k..k+1], b1 = W[n][k+8..k+9]
// ---------------------------------------------------------------------------
__global__ void __launch_bounds__(256) prep_w_kernel(const float* __restrict__ W)
{
    const uint32_t u = blockIdx.x * 256 + threadIdx.x;
    const int lane = u & 31;
    const int ni   = (u >> 5) & 15;
    const int ks   = (u >> 9) & 127;
    const int nt   = u >> 16;

    const int n = nt * 128 + ni * 8 + (lane >> 2);
    const int k = ks * 16 + (lane & 3) * 2;
    const float* b = W + (size_t)n * NIN + k;

    __half h0a, h0b, h1a, h1b, l0a, l0b, l1a, l1b;
    h_split(b[0], h0a, l0a);  h_split(b[1], h0b, l0b);
    h_split(b[8], h1a, l1a);  h_split(b[9], h1b, l1b);

    uint4* dst = (uint4*)g_wpre + ((size_t)nt * 128 + ks) * 512 + ni * 32 + lane;
    __half2* d = (__half2*)dst;
    d[0] = __halves2half2(h0a, h0b);
    d[1] = __halves2half2(h1a, h1b);
    d[2] = __halves2half2(l0a, l0b);
    d[3] = __halves2half2(l1a, l1b);
}

// ---------------------------------------------------------------------------
// GEMM1 on fp16 tensor cores (3-term split), 3-stage cp.async pipeline.
// Tile 128x128x32, 256 threads; warps 4(m) x 2(n), warp tile 32x64.
// Stage = A 16 KB + B 16 KB = 32 KB; 3 stages = 96 KB.
// ---------------------------------------------------------------------------
#define NTS 64                        // k32 stages
#define GEMM1_SMEM (3 * 32768)

__global__ void __launch_bounds__(256, 2)
gemm1_mma_kernel(const float* __restrict__ bias)
{
    extern __shared__ uint4 smq[];    // 3 * 2048 uint4
    const uint32_t smb = smem_u32(smq);
    const int tid  = threadIdx.x;
    const int lane = tid & 31;
    const int wid  = tid >> 5;

    const uint4* gA = (const uint4*)g_apre + (size_t)blockIdx.y * 128 * 512;
    const uint4* gB = (const uint4*)g_wpre + (size_t)blockIdx.x * 128 * 512;

    const int wmi = (wid & 3) * 2;    // m16 tile base
    const int wni = (wid >> 2) * 8;   // n8 tile base

    float acc[2][8][4] = {};

    #define ISSUE(t, s) do {                                                    \
        uint32_t dA = smb + (s) * 32768;                                        \
        const uint4* srcA = gA + (size_t)(t) * 1024;                            \
        const uint4* srcB = gB + (size_t)(t) * 1024;                            \
        _Pragma("unroll")                                                       \
        for (int j = 0; j < 4; ++j) {                                           \
            CP_ASYNC16(dA + (tid + j * 256) * 16, srcA + tid + j * 256);        \
            CP_ASYNC16(dA + 16384 + (tid + j * 256) * 16, srcB + tid + j * 256);\
        }                                                                       \
        CP_COMMIT();                                                            \
    } while (0)

    ISSUE(0, 0);
    ISSUE(1, 1);

    for (int t = 0; t < NTS; ++t) {
        const int s = t % 3;
        if (t == NTS - 1) { CP_WAIT(0); } else { CP_WAIT(1); }
        __syncthreads();
        if (t + 2 < NTS) ISSUE(t + 2, (t + 2) % 3);

        const uint4* sA = smq + s * 2048;
        const uint4* sB = sA + 1024;

        #pragma unroll
        for (int c = 0; c < 2; ++c) {
            uint4 ah[2], al[2];
            #pragma unroll
            for (int mt = 0; mt < 2; ++mt) {
                ah[mt] = sA[c * 512 + (wmi + mt) * 32 + lane];
                al[mt] = sA[c * 512 + 256 + (wmi + mt) * 32 + lane];
            }
            #pragma unroll
            for (int nt = 0; nt < 8; ++nt) {
                const uint4 bv = sB[c * 512 + (wni + nt) * 32 + lane];
                #pragma unroll
                for (int mt = 0; mt < 2; ++mt) {
                    MMA_F16(acc[mt][nt], ah[mt], bv.x, bv.y);
                    MMA_F16(acc[mt][nt], al[mt], bv.x, bv.y);
                    MMA_F16(acc[mt][nt], ah[mt], bv.z, bv.w);
                }
            }
        }
    }
    #undef ISSUE

    // epilogue
    const int bm = blockIdx.y * 128;
    const int bn = blockIdx.x * 128;
    const int r0 = lane >> 2;
    const int c0 = lane & 3;
    #pragma unroll
    for (int mt = 0; mt < 2; ++mt) {
        const int m_lo = bm + (wid & 3) * 32 + mt * 16 + r0;
        #pragma unroll
        for (int nt = 0; nt < 8; ++nt) {
            const int n = bn + (wid >> 2) * 64 + nt * 8 + c0 * 2;
            const float2 bv = *(const float2*)(bias + n);
            float2 v0, v1;
            v0.x = acc[mt][nt][0] + bv.x;
            v0.y = acc[mt][nt][1] + bv.y;
            v1.x = acc[mt][nt][2] + bv.x;
            v1.y = acc[mt][nt][3] + bv.y;
            *(float2*)(g_buf + (size_t)m_lo * NIN + n)       = v0;
            *(float2*)(g_buf + (size_t)(m_lo + 8) * NIN + n) = v1;
        }
    }
}

// ---------------------------------------------------------------------------
// fast exp (x <= 0, x >= ~-30): FFMA-only, rel err ~1e-7, no MUFU.
// ---------------------------------------------------------------------------
__device__ __forceinline__ float fexp(float x) {
    float t = fmaf(x, 1.4426950408889634f, 12582912.0f);
    float j = t - 12582912.0f;
    float f = fmaf(j, -0.693359375f, x);
    f = fmaf(j, 2.1219444005469057e-4f, f);
    float p = 1.3888889e-3f;
    p = fmaf(p, f, 8.3333333e-3f);
    p = fmaf(p, f, 4.1666668e-2f);
    p = fmaf(p, f, 1.6666667e-1f);
    p = fmaf(p, f, 0.5f);
    p = fmaf(p, f, 1.0f);
    p = fmaf(p, f, 1.0f);
    int ji = (int)j;
    return p * __int_as_float((ji + 127) << 23);
}

// ---------------------------------------------------------------------------
// Row-wise: softmax -> fp64 cumsum -> interp. v2:
//  - registers for z, poly exp (no MUFU)
//  - pos staged in smem (double), interp done interleaved (conflict-free gather)
//  - warped staged in smem, coalesced float4 stores
// ---------------------------------------------------------------------------
__global__ void __launch_bounds__(256)
warp_rows_kernel(const float* __restrict__ X)
{
    __shared__ float  sx[NIN];
    __shared__ double spos[NIN];
    __shared__ float  sw[NIN];
    __shared__ float  wred[8];
    __shared__ double wtot[8];

    const int row  = blockIdx.x;
    const int t    = threadIdx.x;
    const int lane = t & 31;
    const int wid  = t >> 5;
    const float* xr = X + (size_t)row * NIN;
    float* zr = g_buf + (size_t)row * NIN;

    // x row -> smem (coalesced float4)
    #pragma unroll
    for (int j = 0; j < 2; ++j)
        ((float4*)sx)[t + j * 256] = ((const float4*)xr)[t + j * 256];

    // z: 8 consecutive per thread, registers
    float zv[8];
    *(float4*)(zv)     = *(const float4*)(zr + t * 8);
    *(float4*)(zv + 4) = *(const float4*)(zr + t * 8 + 4);

    // block max
    float mx = zv[0];
    #pragma unroll
    for (int i = 1; i < 8; ++i) mx = fmaxf(mx, zv[i]);
    #pragma unroll
    for (int d = 16; d; d >>= 1) mx = fmaxf(mx, __shfl_xor_sync(0xffffffffu, mx, d));
    if (lane == 0) wred[wid] = mx;
    __syncthreads();
    float bmax = wred[0];
    #pragma unroll
    for (int i = 1; i < 8; ++i) bmax = fmaxf(bmax, wred[i]);

    // exp + local fp64 cumsum
    double csum[8];
    double run = 0.0;
    #pragma unroll
    for (int i = 0; i < 8; ++i) {
        run += (double)fexp(zv[i] - bmax);
        csum[i] = run;
    }

    // block-wide fp64 scan of per-thread totals
    double v = run;
    #pragma unroll
    for (int d = 1; d < 32; d <<= 1) {
        double u = __shfl_up_sync(0xffffffffu, v, d);
        if (lane >= d) v += u;
    }
    if (lane == 31) wtot[wid] = v;
    __syncthreads();
    double total = 0.0, woff = 0.0;
    #pragma unroll
    for (int i = 0; i < 8; ++i) {         // fixed order: identical on all threads
        if (i == wid) woff = total;
        total += wtot[i];
    }
    const double toff = woff + (v - run);
    const double invs = (double)(NIN - 1) / total;

    // pos -> smem
    #pragma unroll
    for (int i = 0; i < 8; ++i) {
        double pos = (toff + csum[i]) * invs;
        pos = fmin(pos, (double)(NIN - 1));
        spos[t * 8 + i] = pos;
    }
    __syncthreads();

    // interleaved interp: lanes read near-consecutive knots -> few conflicts
    #pragma unroll
    for (int j = 0; j < 8; ++j) {
        const int i = t + j * 256;
        const double pos = spos[i];
        int idx = (int)pos;
        if (idx > NIN - 2) idx = NIN - 2;
        const float w  = (float)(pos - (double)idx);
        const float y0 = sx[idx], y1 = sx[idx + 1];
        sw[i] = fmaf(w, y1 - y0, y0);
    }
    __syncthreads();

    // coalesced store
    #pragma unroll
    for (int j = 0; j < 2; ++j)
        ((float4*)zr)[t + j * 256] = ((const float4*)sw)[t + j * 256];
}

// ---------------------------------------------------------------------------
// GEMM2: out[r,c] = sum_k warped[r,k] * F[c,k] + fb[c]
// Tile 32 rows x 112 cols x 32 K; 128 threads, 4x7/thread; 512 blocks.
// ---------------------------------------------------------------------------
__global__ void __launch_bounds__(128)
gemm2_kernel(const float* __restrict__ F, const float* __restrict__ fb,
             float* __restrict__ out)
{
    __shared__ float As[32][36];
    __shared__ float Bs[32][113];

    const int tid  = threadIdx.x;
    const int row0 = blockIdx.x * 32;
    const int tx   = tid & 15;
    const int ty   = tid >> 4;

    float acc[4][7] = {};

    for (int k0 = 0; k0 < NIN; k0 += 32) {
        #pragma unroll
        for (int i = 0; i < 2; ++i) {
            int f  = tid + i * 128;      // 256 float4 = 32x32 A tile
            int r  = f >> 3;
            int k4 = (f & 7) << 2;
            float4 v = *(const float4*)(g_buf + (size_t)(row0 + r) * NIN + k0 + k4);
            As[k4 + 0][r] = v.x; As[k4 + 1][r] = v.y;
            As[k4 + 2][r] = v.z; As[k4 + 3][r] = v.w;
        }
        #pragma unroll
        for (int i = 0; i < 7; ++i) {    // 896 float4 = 112x32 B tile
            int f  = tid + i * 128;
            int c  = f >> 3;
            int k4 = (f & 7) << 2;
            float4 v = (c < NCLS)
                ? *(const float4*)(F + (size_t)c * NIN + k0 + k4)
                : make_float4(0.f, 0.f, 0.f, 0.f);
            Bs[k4 + 0][c] = v.x; Bs[k4 + 1][c] = v.y;
            Bs[k4 + 2][c] = v.z; Bs[k4 + 3][c] = v.w;
        }
        __syncthreads();

        #pragma unroll
        for (int k = 0; k < 32; ++k) {
            float a[4];
            *(float4*)a = *(const float4*)&As[k][ty * 4];
            float b[7];
            #pragma unroll
            for (int j = 0; j < 7; ++j) b[j] = Bs[k][tx * 7 + j];
            #pragma unroll
            for (int i = 0; i < 4; ++i)
                #pragma unroll
                for (int j = 0; j < 7; ++j)
                    acc[i][j] = fmaf(a[i], b[j], acc[i][j]);
        }
        __syncthreads();
    }

    #pragma unroll
    for (int i = 0; i < 4; ++i) {
        int r = row0 + ty * 4 + i;
        #pragma unroll
        for (int j = 0; j < 7; ++j) {
            int c = tx * 7 + j;
            if (c < NCLS) out[(size_t)r * NCLS + c] = acc[i][j] + fb[c];
        }
    }
}

// ---------------------------------------------------------------------------
extern "C" void kernel_launch(void* const* d_in, const int* in_sizes, int n_in,
                              void* d_out, int out_size)
{
    const float* x  = (const float*)d_in[0];  // time_series [16384, 2048]
    const float* w  = (const float*)d_in[1];  // w_weight    [2048, 2048]
    const float* wb = (const float*)d_in[2];  // w_bias      [2048]
    const float* fw = (const float*)d_in[3];  // fc_weight   [100, 2048]
    const float* fb = (const float*)d_in[4];  // fc_bias     [100]
    float* out = (float*)d_out;               // [16384, 100]

    cudaFuncSetAttribute(gemm1_mma_kernel,
                         cudaFuncAttributeMaxDynamicSharedMemorySize, GEMM1_SMEM);

    prep_a_kernel<<<16384, 256>>>(x);         // 128mt x 128ks x 8mi x 32 lanes
    prep_w_kernel<<<4096, 256>>>(w);          // 16nt x 128ks x 16ni x 32 lanes

    dim3 g1(NIN / 128, NROWS / 128);          // 16 x 128
    gemm1_mma_kernel<<<g1, 256, GEMM1_SMEM>>>(wb);
    warp_rows_kernel<<<NROWS, 256>>>(x);
    gemm2_kernel<<<NROWS / 32, 128>>>(fw, fb, out);
}

// round 7
// speedup vs baseline: 2.8989x; 1.5186x over previous
#include <cuda_runtime.h>
#include <cuda_fp16.h>
#include <math.h>
#include <stdint.h>

#define NROWS 16384
#define NIN   2048
#define NCLS  100

// Scratch
static __device__ float  g_buf[(size_t)NROWS * NIN];          // z, then warped
static __device__ __half g_apre[(size_t)NROWS * NIN * 2];     // A hi/lo fp16 frags
static __device__ __half g_wpre[(size_t)NIN * NIN * 2];       // W hi/lo fp16 frags

// ---------------------------------------------------------------------------
// helpers
// ---------------------------------------------------------------------------
__device__ __forceinline__ uint32_t smem_u32(const void* p) {
    uint32_t a;
    asm("{ .reg .u64 t; cvta.to.shared.u64 t, %1; cvt.u32.u64 %0, t; }" : "=r"(a) : "l"(p));
    return a;
}

__device__ __forceinline__ void h_split(float x, __half& h, __half& l) {
    h = __float2half_rn(x);
    l = __float2half_rn(x - __half2float(h));
}

#define MMA_F16(d, a, b0, b1)                                               \
    asm volatile("mma.sync.aligned.m16n8k16.row.col.f32.f16.f16.f32 "       \
                 "{%0,%1,%2,%3}, {%4,%5,%6,%7}, {%8,%9}, {%0,%1,%2,%3};"    \
                 : "+f"((d)[0]), "+f"((d)[1]), "+f"((d)[2]), "+f"((d)[3])   \
                 : "r"((a).x), "r"((a).y), "r"((a).z), "r"((a).w),          \
                   "r"(b0), "r"(b1))

#define CP_ASYNC16(dst, src) \
    asm volatile("cp.async.cg.shared.global [%0], [%1], 16;" :: "r"(dst), "l"(src) : "memory")
#define CP_COMMIT()  asm volatile("cp.async.commit_group;" ::: "memory")
#define CP_WAIT(n)   asm volatile("cp.async.wait_group %0;" :: "n"(n) : "memory")

// two-float (double-single) compensated add, FFMA pipe only
__device__ __forceinline__ float2 df_add(float2 a, float2 b) {
    float s  = a.x + b.x;
    float bb = s - a.x;
    float e  = (a.x - (s - bb)) + (b.x - bb);
    e += a.y + b.y;
    float hi = s + e;
    float lo = e - (hi - s);
    return make_float2(hi, lo);
}

// ---------------------------------------------------------------------------
// Prep A: split x into hi/lo fp16 limbs, fragment-permuted for m16n8k16.
// ---------------------------------------------------------------------------
__global__ void __launch_bounds__(256) prep_a_kernel(const float* __restrict__ A)
{
    const uint32_t u = blockIdx.x * 256 + threadIdx.x;
    const int lane = u & 31;
    const int mi   = (u >> 5) & 7;
    const int ks   = (u >> 8) & 127;
    const int mt   = u >> 15;

    const int r = mt * 128 + mi * 16 + (lane >> 2);
    const int c = ks * 16 + (lane & 3) * 2;
    const float* a0p = A + (size_t)r * NIN + c;
    const float* a1p = a0p + (size_t)8 * NIN;

    __half h[8], l[8];
    h_split(a0p[0], h[0], l[0]);  h_split(a0p[1], h[1], l[1]);
    h_split(a1p[0], h[2], l[2]);  h_split(a1p[1], h[3], l[3]);
    h_split(a0p[8], h[4], l[4]);  h_split(a0p[9], h[5], l[5]);
    h_split(a1p[8], h[6], l[6]);  h_split(a1p[9], h[7], l[7]);

    uint4* dst = (uint4*)g_apre + ((size_t)mt * 128 + ks) * 512 + mi * 32 + lane;
    __half2* dh = (__half2*)dst;
    dh[0] = __halves2half2(h[0], h[1]); dh[1] = __halves2half2(h[2], h[3]);
    dh[2] = __halves2half2(h[4], h[5]); dh[3] = __halves2half2(h[6], h[7]);
    __half2* dl = (__half2*)(dst + 256);
    dl[0] = __halves2half2(l[0], l[1]); dl[1] = __halves2half2(l[2], l[3]);
    dl[2] = __halves2half2(l[4], l[5]); dl[3] = __halves2half2(l[6], l[7]);
}

// ---------------------------------------------------------------------------
// Prep W
// ---------------------------------------------------------------------------
__global__ void __launch_bounds__(256) prep_w_kernel(const float* __restrict__ W)
{
    const uint32_t u = blockIdx.x * 256 + threadIdx.x;
    const int lane = u & 31;
    const int ni   = (u >> 5) & 15;
    const int ks   = (u >> 9) & 127;
    const int nt   = u >> 16;

    const int n = nt * 128 + ni * 8 + (lane >> 2);
    const int k = ks * 16 + (lane & 3) * 2;
    const float* b = W + (size_t)n * NIN + k;

    __half h0a, h0b, h1a, h1b, l0a, l0b, l1a, l1b;
    h_split(b[0], h0a, l0a);  h_split(b[1], h0b, l0b);
    h_split(b[8], h1a, l1a);  h_split(b[9], h1b, l1b);

    uint4* dst = (uint4*)g_wpre + ((size_t)nt * 128 + ks) * 512 + ni * 32 + lane;
    __half2* d = (__half2*)dst;
    d[0] = __halves2half2(h0a, h0b);
    d[1] = __halves2half2(h1a, h1b);
    d[2] = __halves2half2(l0a, l0b);
    d[3] = __halves2half2(l1a, l1b);
}

// ---------------------------------------------------------------------------
// GEMM1 on fp16 tensor cores (3-term split), 3-stage cp.async pipeline.
// ---------------------------------------------------------------------------
#define NTS 64
#define GEMM1_SMEM (3 * 32768)

__global__ void __launch_bounds__(256, 2)
gemm1_mma_kernel(const float* __restrict__ bias)
{
    extern __shared__ uint4 smq[];
    const uint32_t smb = smem_u32(smq);
    const int tid  = threadIdx.x;
    const int lane = tid & 31;
    const int wid  = tid >> 5;

    const uint4* gA = (const uint4*)g_apre + (size_t)blockIdx.y * 128 * 512;
    const uint4* gB = (const uint4*)g_wpre + (size_t)blockIdx.x * 128 * 512;

    const int wmi = (wid & 3) * 2;
    const int wni = (wid >> 2) * 8;

    float acc[2][8][4] = {};

    #define ISSUE(t, s) do {                                                    \
        uint32_t dA = smb + (s) * 32768;                                        \
        const uint4* srcA = gA + (size_t)(t) * 1024;                            \
        const uint4* srcB = gB + (size_t)(t) * 1024;                            \
        _Pragma("unroll")                                                       \
        for (int j = 0; j < 4; ++j) {                                           \
            CP_ASYNC16(dA + (tid + j * 256) * 16, srcA + tid + j * 256);        \
            CP_ASYNC16(dA + 16384 + (tid + j * 256) * 16, srcB + tid + j * 256);\
        }                                                                       \
        CP_COMMIT();                                                            \
    } while (0)

    ISSUE(0, 0);
    ISSUE(1, 1);

    for (int t = 0; t < NTS; ++t) {
        const int s = t % 3;
        if (t == NTS - 1) { CP_WAIT(0); } else { CP_WAIT(1); }
        __syncthreads();
        if (t + 2 < NTS) ISSUE(t + 2, (t + 2) % 3);

        const uint4* sA = smq + s * 2048;
        const uint4* sB = sA + 1024;

        #pragma unroll
        for (int c = 0; c < 2; ++c) {
            uint4 ah[2], al[2];
            #pragma unroll
            for (int mt = 0; mt < 2; ++mt) {
                ah[mt] = sA[c * 512 + (wmi + mt) * 32 + lane];
                al[mt] = sA[c * 512 + 256 + (wmi + mt) * 32 + lane];
            }
            #pragma unroll
            for (int nt = 0; nt < 8; ++nt) {
                const uint4 bv = sB[c * 512 + (wni + nt) * 32 + lane];
                #pragma unroll
                for (int mt = 0; mt < 2; ++mt) {
                    MMA_F16(acc[mt][nt], ah[mt], bv.x, bv.y);
                    MMA_F16(acc[mt][nt], al[mt], bv.x, bv.y);
                    MMA_F16(acc[mt][nt], ah[mt], bv.z, bv.w);
                }
            }
        }
    }
    #undef ISSUE

    const int bm = blockIdx.y * 128;
    const int bn = blockIdx.x * 128;
    const int r0 = lane >> 2;
    const int c0 = lane & 3;
    #pragma unroll
    for (int mt = 0; mt < 2; ++mt) {
        const int m_lo = bm + (wid & 3) * 32 + mt * 16 + r0;
        #pragma unroll
        for (int nt = 0; nt < 8; ++nt) {
            const int n = bn + (wid >> 2) * 64 + nt * 8 + c0 * 2;
            const float2 bv = *(const float2*)(bias + n);
            float2 v0, v1;
            v0.x = acc[mt][nt][0] + bv.x;
            v0.y = acc[mt][nt][1] + bv.y;
            v1.x = acc[mt][nt][2] + bv.x;
            v1.y = acc[mt][nt][3] + bv.y;
            *(float2*)(g_buf + (size_t)m_lo * NIN + n)       = v0;
            *(float2*)(g_buf + (size_t)(m_lo + 8) * NIN + n) = v1;
        }
    }
}

// ---------------------------------------------------------------------------
// fast exp (x <= 0): FFMA/ALU only — no MUFU, no F2I.
// ---------------------------------------------------------------------------
__device__ __forceinline__ float fexp(float x) {
    float t = fmaf(x, 1.4426950408889634f, 12582912.0f);
    int ji = __float_as_int(t) - 0x4B400000;     // integer j via mantissa bits
    float j = t - 12582912.0f;
    float f = fmaf(j, -0.693359375f, x);
    f = fmaf(j, 2.1219444005469057e-4f, f);
    float p = 1.3888889e-3f;
    p = fmaf(p, f, 8.3333333e-3f);
    p = fmaf(p, f, 4.1666668e-2f);
    p = fmaf(p, f, 1.6666667e-1f);
    p = fmaf(p, f, 0.5f);
    p = fmaf(p, f, 1.0f);
    p = fmaf(p, f, 1.0f);
    return p * __int_as_float((ji + 127) << 23);
}

// ---------------------------------------------------------------------------
// Row-wise: softmax -> cumsum -> interp. v3: ZERO fp64.
// Local fp32 cumsum; thread-offset scan in two-float compensated arithmetic.
// ---------------------------------------------------------------------------
__global__ void __launch_bounds__(256)
warp_rows_kernel(const float* __restrict__ X)
{
    __shared__ float  sx[NIN];
    __shared__ float  spos[NIN];
    __shared__ float  wred[8];
    __shared__ float2 wtot[8];

    const int row  = blockIdx.x;
    const int t    = threadIdx.x;
    const int lane = t & 31;
    const int wid  = t >> 5;
    const float* xr = X + (size_t)row * NIN;
    float* zr = g_buf + (size_t)row * NIN;

    // x row -> smem (coalesced float4)
    #pragma unroll
    for (int j = 0; j < 2; ++j)
        ((float4*)sx)[t + j * 256] = ((const float4*)xr)[t + j * 256];

    // z: 8 consecutive per thread, registers
    float zv[8];
    *(float4*)(zv)     = *(const float4*)(zr + t * 8);
    *(float4*)(zv + 4) = *(const float4*)(zr + t * 8 + 4);

    // block max
    float mx = zv[0];
    #pragma unroll
    for (int i = 1; i < 8; ++i) mx = fmaxf(mx, zv[i]);
    #pragma unroll
    for (int d = 16; d; d >>= 1) mx = fmaxf(mx, __shfl_xor_sync(0xffffffffu, mx, d));
    if (lane == 0) wred[wid] = mx;
    __syncthreads();
    float bmax = wred[0];
    #pragma unroll
    for (int i = 1; i < 8; ++i) bmax = fmaxf(bmax, wred[i]);

    // exp + local fp32 inclusive cumsum (local partials are small -> tiny abs err)
    float csum[8];
    float run = 0.0f;
    #pragma unroll
    for (int i = 0; i < 8; ++i) {
        run += fexp(zv[i] - bmax);
        csum[i] = run;
    }

    // warp-level two-float inclusive scan of per-thread totals
    float2 v = make_float2(run, 0.0f);
    #pragma unroll
    for (int d = 1; d < 32; d <<= 1) {
        float uh = __shfl_up_sync(0xffffffffu, v.x, d);
        float ul = __shfl_up_sync(0xffffffffu, v.y, d);
        if (lane >= d) v = df_add(v, make_float2(uh, ul));
    }
    if (lane == 31) wtot[wid] = v;
    __syncthreads();

    // block combine (fixed order, identical on all threads)
    float2 tot  = make_float2(0.0f, 0.0f);
    float2 woff = make_float2(0.0f, 0.0f);
    #pragma unroll
    for (int i = 0; i < 8; ++i) {
        if (i == wid) woff = tot;
        tot = df_add(tot, wtot[i]);
    }
    // exclusive thread offset = woff + (v - run)
    float2 ex   = df_add(v, make_float2(-run, 0.0f));
    float2 base = df_add(woff, ex);

    const float totf = tot.x + tot.y;
    const float invs = (float)(NIN - 1) / totf;

    // pos in fp32 -> smem
    #pragma unroll
    for (int i = 0; i < 8; ++i) {
        float g = base.x + (base.y + csum[i]);      // small terms first
        float pos = fminf(g * invs, (float)(NIN - 1));
        spos[t * 8 + i] = pos;
    }
    __syncthreads();

    // interleaved interp (conflict-free gather) + direct coalesced stores
    #pragma unroll
    for (int j = 0; j < 8; ++j) {
        const int i = t + j * 256;
        const float pos = spos[i];
        float flf = fminf(floorf(pos), (float)(NIN - 2));
        const int idx = (int)flf;
        const float w  = pos - flf;
        const float y0 = sx[idx], y1 = sx[idx + 1];
        zr[i] = fmaf(w, y1 - y0, y0);
    }
}

// ---------------------------------------------------------------------------
// GEMM2: out[r,c] = sum_k warped[r,k] * F[c,k] + fb[c]
// ---------------------------------------------------------------------------
__global__ void __launch_bounds__(128)
gemm2_kernel(const float* __restrict__ F, const float* __restrict__ fb,
             float* __restrict__ out)
{
    __shared__ float As[32][36];
    __shared__ float Bs[32][113];

    const int tid  = threadIdx.x;
    const int row0 = blockIdx.x * 32;
    const int tx   = tid & 15;
    const int ty   = tid >> 4;

    float acc[4][7] = {};

    for (int k0 = 0; k0 < NIN; k0 += 32) {
        #pragma unroll
        for (int i = 0; i < 2; ++i) {
            int f  = tid + i * 128;
            int r  = f >> 3;
            int k4 = (f & 7) << 2;
            float4 v = *(const float4*)(g_buf + (size_t)(row0 + r) * NIN + k0 + k4);
            As[k4 + 0][r] = v.x; As[k4 + 1][r] = v.y;
            As[k4 + 2][r] = v.z; As[k4 + 3][r] = v.w;
        }
        #pragma unroll
        for (int i = 0; i < 7; ++i) {
            int f  = tid + i * 128;
            int c  = f >> 3;
            int k4 = (f & 7) << 2;
            float4 v = (c < NCLS)
                ? *(const float4*)(F + (size_t)c * NIN + k0 + k4)
                : make_float4(0.f, 0.f, 0.f, 0.f);
            Bs[k4 + 0][c] = v.x; Bs[k4 + 1][c] = v.y;
            Bs[k4 + 2][c] = v.z; Bs[k4 + 3][c] = v.w;
        }
        __syncthreads();

        #pragma unroll
        for (int k = 0; k < 32; ++k) {
            float a[4];
            *(float4*)a = *(const float4*)&As[k][ty * 4];
            float b[7];
            #pragma unroll
            for (int j = 0; j < 7; ++j) b[j] = Bs[k][tx * 7 + j];
            #pragma unroll
            for (int i = 0; i < 4; ++i)
                #pragma unroll
                for (int j = 0; j < 7; ++j)
                    acc[i][j] = fmaf(a[i], b[j], acc[i][j]);
        }
        __syncthreads();
    }

    #pragma unroll
    for (int i = 0; i < 4; ++i) {
        int r = row0 + ty * 4 + i;
        #pragma unroll
        for (int j = 0; j < 7; ++j) {
            int c = tx * 7 + j;
            if (c < NCLS) out[(size_t)r * NCLS + c] = acc[i][j] + fb[c];
        }
    }
}

// ---------------------------------------------------------------------------
extern "C" void kernel_launch(void* const* d_in, const int* in_sizes, int n_in,
                              void* d_out, int out_size)
{
    const float* x  = (const float*)d_in[0];
    const float* w  = (const float*)d_in[1];
    const float* wb = (const float*)d_in[2];
    const float* fw = (const float*)d_in[3];
    const float* fb = (const float*)d_in[4];
    float* out = (float*)d_out;

    cudaFuncSetAttribute(gemm1_mma_kernel,
                         cudaFuncAttributeMaxDynamicSharedMemorySize, GEMM1_SMEM);

    prep_a_kernel<<<16384, 256>>>(x);
    prep_w_kernel<<<4096, 256>>>(w);

    dim3 g1(NIN / 128, NROWS / 128);
    gemm1_mma_kernel<<<g1, 256, GEMM1_SMEM>>>(wb);
    warp_rows_kernel<<<NROWS, 256>>>(x);
    gemm2_kernel<<<NROWS / 32, 128>>>(fw, fb, out);
}

// round 8
// speedup vs baseline: 3.3585x; 1.1585x over previous
#include <cuda_runtime.h>
#include <cuda_fp16.h>
#include <math.h>
#include <stdint.h>

#define NROWS 16384
#define NIN   2048
#define NCLS  100

// Scratch
static __device__ float  g_buf[(size_t)NROWS * NIN];          // z, then warped
static __device__ __half g_apre[(size_t)NROWS * NIN * 2];     // A hi/lo fp16 frags
static __device__ __half g_wpre[(size_t)NIN * NIN * 2];       // W hi/lo fp16 frags
static __device__ __half g_fpre[(size_t)128 * 448 * 8];       // fc hi/lo frags (112xN pad)

// ---------------------------------------------------------------------------
// helpers
// ---------------------------------------------------------------------------
__device__ __forceinline__ uint32_t smem_u32(const void* p) {
    uint32_t a;
    asm("{ .reg .u64 t; cvta.to.shared.u64 t, %1; cvt.u32.u64 %0, t; }" : "=r"(a) : "l"(p));
    return a;
}

__device__ __forceinline__ void h_split(float x, __half& h, __half& l) {
    h = __float2half_rn(x);
    l = __float2half_rn(x - __half2float(h));
}

// split two floats -> packed hi half2 and lo half2 (as u32)
__device__ __forceinline__ void split2(float a, float b, uint32_t& hi, uint32_t& lo) {
    __half ha, la, hb, lb;
    h_split(a, ha, la);
    h_split(b, hb, lb);
    __half2 h2 = __halves2half2(ha, hb);
    __half2 l2 = __halves2half2(la, lb);
    hi = *(uint32_t*)&h2;
    lo = *(uint32_t*)&l2;
}

#define MMA_F16(d, a, b0, b1)                                               \
    asm volatile("mma.sync.aligned.m16n8k16.row.col.f32.f16.f16.f32 "       \
                 "{%0,%1,%2,%3}, {%4,%5,%6,%7}, {%8,%9}, {%0,%1,%2,%3};"    \
                 : "+f"((d)[0]), "+f"((d)[1]), "+f"((d)[2]), "+f"((d)[3])   \
                 : "r"((a).x), "r"((a).y), "r"((a).z), "r"((a).w),          \
                   "r"(b0), "r"(b1))

#define CP_ASYNC16(dst, src) \
    asm volatile("cp.async.cg.shared.global [%0], [%1], 16;" :: "r"(dst), "l"(src) : "memory")
#define CP_COMMIT()  asm volatile("cp.async.commit_group;" ::: "memory")
#define CP_WAIT(n)   asm volatile("cp.async.wait_group %0;" :: "n"(n) : "memory")

// two-float compensated add (FFMA pipe only)
__device__ __forceinline__ float2 df_add(float2 a, float2 b) {
    float s  = a.x + b.x;
    float bb = s - a.x;
    float e  = (a.x - (s - bb)) + (b.x - bb);
    e += a.y + b.y;
    float hi = s + e;
    float lo = e - (hi - s);
    return make_float2(hi, lo);
}

// ---------------------------------------------------------------------------
// Prep A: split x into hi/lo fp16 limbs, fragment-permuted for m16n8k16.
// Chunk (mt,ks) = (mt*128+ks)*512 uint4: [hi: mi(8) x lane] then [lo: same].
// ---------------------------------------------------------------------------
__global__ void __launch_bounds__(256) prep_a_kernel(const float* __restrict__ A)
{
    const uint32_t u = blockIdx.x * 256 + threadIdx.x;
    const int lane = u & 31;
    const int mi   = (u >> 5) & 7;
    const int ks   = (u >> 8) & 127;
    const int mt   = u >> 15;

    const int r = mt * 128 + mi * 16 + (lane >> 2);
    const int c = ks * 16 + (lane & 3) * 2;
    const float* a0p = A + (size_t)r * NIN + c;
    const float* a1p = a0p + (size_t)8 * NIN;

    uint4 hv, lv;
    split2(a0p[0], a0p[1], hv.x, lv.x);
    split2(a1p[0], a1p[1], hv.y, lv.y);
    split2(a0p[8], a0p[9], hv.z, lv.z);
    split2(a1p[8], a1p[9], hv.w, lv.w);

    uint4* dst = (uint4*)g_apre + ((size_t)mt * 128 + ks) * 512 + mi * 32 + lane;
    dst[0]   = hv;
    dst[256] = lv;
}

// ---------------------------------------------------------------------------
// Prep W: chunk (nt,ks) = (nt*128+ks)*512 uint4: [ni(16) x lane] of
// {bh0,bh1,bl0,bl1}.
// ---------------------------------------------------------------------------
__global__ void __launch_bounds__(256) prep_w_kernel(const float* __restrict__ W)
{
    const uint32_t u = blockIdx.x * 256 + threadIdx.x;
    const int lane = u & 31;
    const int ni   = (u >> 5) & 15;
    const int ks   = (u >> 9) & 127;
    const int nt   = u >> 16;

    const int n = nt * 128 + ni * 8 + (lane >> 2);
    const int k = ks * 16 + (lane & 3) * 2;
    const float* b = W + (size_t)n * NIN + k;

    uint4 o;
    split2(b[0], b[1], o.x, o.z);
    split2(b[8], b[9], o.y, o.w);

    uint4* dst = (uint4*)g_wpre + ((size_t)nt * 128 + ks) * 512 + ni * 32 + lane;
    *dst = o;
}

// ---------------------------------------------------------------------------
// Prep F: fc_weight [100,2048] -> fragment layout, N padded to 112.
// Chunk ks: 14 ni x 32 lanes of {bh0,bh1,bl0,bl1} at (ks*448 + ni*32 + lane).
// ---------------------------------------------------------------------------
__global__ void __launch_bounds__(448) prep_f_kernel(const float* __restrict__ F)
{
    const int lane = threadIdx.x & 31;
    const int ni   = threadIdx.x >> 5;      // 0..13
    const int ks   = blockIdx.x;            // 0..127

    const int n = ni * 8 + (lane >> 2);
    const int k = ks * 16 + (lane & 3) * 2;

    float v0 = 0.f, v1 = 0.f, v2 = 0.f, v3 = 0.f;
    if (n < NCLS) {
        const float* p = F + (size_t)n * NIN + k;
        v0 = p[0]; v1 = p[1]; v2 = p[8]; v3 = p[9];
    }
    uint4 o;
    split2(v0, v1, o.x, o.z);
    split2(v2, v3, o.y, o.w);
    ((uint4*)g_fpre)[ks * 448 + ni * 32 + lane] = o;
}

// ---------------------------------------------------------------------------
// GEMM1: fp16 tensor cores, 3-term split. CTA tile 256x128, 256 threads,
// warps 4(m) x 2(n) -> warp tile 64x64. 3-stage cp.async, 48 KB/stage.
// ---------------------------------------------------------------------------
#define NTS 64
#define G1_STG 3072                       // uint4 per stage
#define GEMM1_SMEM (3 * 49152)

__global__ void __launch_bounds__(256, 1)
gemm1_mma_kernel(const float* __restrict__ bias)
{
    extern __shared__ uint4 smq[];
    const uint32_t smb = smem_u32(smq);
    const int tid  = threadIdx.x;
    const int lane = tid & 31;
    const int wid  = tid >> 5;

    const uint4* gA = (const uint4*)g_apre + (size_t)blockIdx.y * 2 * 128 * 512;
    const uint4* gB = (const uint4*)g_wpre + (size_t)blockIdx.x * 128 * 512;

    const int wm = wid & 3;               // 0..3, 64 rows each
    const int wn = wid >> 2;              // 0..1, 64 cols each

    float acc[4][8][4] = {};

    #define ISSUE(t, s) do {                                                     \
        uint32_t d = smb + (s) * 49152;                                          \
        _Pragma("unroll")                                                        \
        for (int j = 0; j < 2; ++j) {                                            \
            int idx = tid + j * 256;                                             \
            CP_ASYNC16(d + (0 * 512 + idx) * 16, gA + (0 + 2 * (t)) * 512 + idx);\
            CP_ASYNC16(d + (1 * 512 + idx) * 16, gA + (1 + 2 * (t)) * 512 + idx);\
            CP_ASYNC16(d + (2 * 512 + idx) * 16, gA + (128 + 2 * (t)) * 512 + idx);\
            CP_ASYNC16(d + (3 * 512 + idx) * 16, gA + (129 + 2 * (t)) * 512 + idx);\
            CP_ASYNC16(d + (4 * 512 + idx) * 16, gB + (0 + 2 * (t)) * 512 + idx);\
            CP_ASYNC16(d + (5 * 512 + idx) * 16, gB + (1 + 2 * (t)) * 512 + idx);\
        }                                                                        \
        CP_COMMIT();                                                             \
    } while (0)

    ISSUE(0, 0);
    ISSUE(1, 1);

    for (int t = 0; t < NTS; ++t) {
        const int s = t % 3;
        if (t == NTS - 1) { CP_WAIT(0); } else { CP_WAIT(1); }
        __syncthreads();
        if (t + 2 < NTS) ISSUE(t + 2, (t + 2) % 3);

        const uint4* st = smq + s * G1_STG;

        #pragma unroll
        for (int c = 0; c < 2; ++c) {
            uint4 ah[4], al[4];
            #pragma unroll
            for (int mt = 0; mt < 4; ++mt) {
                const int mi_cta = wm * 4 + mt;
                const uint4* chunk = st + ((mi_cta >> 3) * 2 + c) * 512;
                const int o = (mi_cta & 7) * 32 + lane;
                ah[mt] = chunk[o];
                al[mt] = chunk[256 + o];
            }
            #pragma unroll
            for (int nt = 0; nt < 8; ++nt) {
                const uint4 bv = st[2048 + c * 512 + (wn * 8 + nt) * 32 + lane];
                #pragma unroll
                for (int mt = 0; mt < 4; ++mt) {
                    MMA_F16(acc[mt][nt], ah[mt], bv.x, bv.y);
                    MMA_F16(acc[mt][nt], al[mt], bv.x, bv.y);
                    MMA_F16(acc[mt][nt], ah[mt], bv.z, bv.w);
                }
            }
        }
    }
    #undef ISSUE

    // epilogue
    const int bm = blockIdx.y * 256;
    const int bn = blockIdx.x * 128;
    const int r0 = lane >> 2;
    const int c0 = lane & 3;
    #pragma unroll
    for (int mt = 0; mt < 4; ++mt) {
        const int m_lo = bm + wm * 64 + mt * 16 + r0;
        #pragma unroll
        for (int nt = 0; nt < 8; ++nt) {
            const int n = bn + wn * 64 + nt * 8 + c0 * 2;
            const float2 bv = *(const float2*)(bias + n);
            float2 v0, v1;
            v0.x = acc[mt][nt][0] + bv.x;
            v0.y = acc[mt][nt][1] + bv.y;
            v1.x = acc[mt][nt][2] + bv.x;
            v1.y = acc[mt][nt][3] + bv.y;
            *(float2*)(g_buf + (size_t)m_lo * NIN + n)       = v0;
            *(float2*)(g_buf + (size_t)(m_lo + 8) * NIN + n) = v1;
        }
    }
}

// ---------------------------------------------------------------------------
// fast exp (x <= 0): FFMA/ALU only.
// ---------------------------------------------------------------------------
__device__ __forceinline__ float fexp(float x) {
    float t = fmaf(x, 1.4426950408889634f, 12582912.0f);
    int ji = __float_as_int(t) - 0x4B400000;
    float j = t - 12582912.0f;
    float f = fmaf(j, -0.693359375f, x);
    f = fmaf(j, 2.1219444005469057e-4f, f);
    float p = 1.3888889e-3f;
    p = fmaf(p, f, 8.3333333e-3f);
    p = fmaf(p, f, 4.1666668e-2f);
    p = fmaf(p, f, 1.6666667e-1f);
    p = fmaf(p, f, 0.5f);
    p = fmaf(p, f, 1.0f);
    p = fmaf(p, f, 1.0f);
    return p * __int_as_float((ji + 127) << 23);
}

// ---------------------------------------------------------------------------
// Row-wise: softmax -> compensated fp32 cumsum -> interp (no fp64).
// ---------------------------------------------------------------------------
__global__ void __launch_bounds__(256)
warp_rows_kernel(const float* __restrict__ X)
{
    __shared__ float  sx[NIN];
    __shared__ float  spos[NIN];
    __shared__ float  wred[8];
    __shared__ float2 wtot[8];

    const int row  = blockIdx.x;
    const int t    = threadIdx.x;
    const int lane = t & 31;
    const int wid  = t >> 5;
    const float* xr = X + (size_t)row * NIN;
    float* zr = g_buf + (size_t)row * NIN;

    #pragma unroll
    for (int j = 0; j < 2; ++j)
        ((float4*)sx)[t + j * 256] = ((const float4*)xr)[t + j * 256];

    float zv[8];
    *(float4*)(zv)     = *(const float4*)(zr + t * 8);
    *(float4*)(zv + 4) = *(const float4*)(zr + t * 8 + 4);

    float mx = zv[0];
    #pragma unroll
    for (int i = 1; i < 8; ++i) mx = fmaxf(mx, zv[i]);
    #pragma unroll
    for (int d = 16; d; d >>= 1) mx = fmaxf(mx, __shfl_xor_sync(0xffffffffu, mx, d));
    if (lane == 0) wred[wid] = mx;
    __syncthreads();
    float bmax = wred[0];
    #pragma unroll
    for (int i = 1; i < 8; ++i) bmax = fmaxf(bmax, wred[i]);

    float csum[8];
    float run = 0.0f;
    #pragma unroll
    for (int i = 0; i < 8; ++i) {
        run += fexp(zv[i] - bmax);
        csum[i] = run;
    }

    float2 v = make_float2(run, 0.0f);
    #pragma unroll
    for (int d = 1; d < 32; d <<= 1) {
        float uh = __shfl_up_sync(0xffffffffu, v.x, d);
        float ul = __shfl_up_sync(0xffffffffu, v.y, d);
        if (lane >= d) v = df_add(v, make_float2(uh, ul));
    }
    if (lane == 31) wtot[wid] = v;
    __syncthreads();

    float2 tot  = make_float2(0.0f, 0.0f);
    float2 woff = make_float2(0.0f, 0.0f);
    #pragma unroll
    for (int i = 0; i < 8; ++i) {
        if (i == wid) woff = tot;
        tot = df_add(tot, wtot[i]);
    }
    float2 ex   = df_add(v, make_float2(-run, 0.0f));
    float2 base = df_add(woff, ex);

    const float totf = tot.x + tot.y;
    const float invs = (float)(NIN - 1) / totf;

    #pragma unroll
    for (int i = 0; i < 8; ++i) {
        float g = base.x + (base.y + csum[i]);
        float pos = fminf(g * invs, (float)(NIN - 1));
        spos[t * 8 + i] = pos;
    }
    __syncthreads();

    #pragma unroll
    for (int j = 0; j < 8; ++j) {
        const int i = t + j * 256;
        const float pos = spos[i];
        float flf = fminf(floorf(pos), (float)(NIN - 2));
        const int idx = (int)flf;
        const float w  = pos - flf;
        const float y0 = sx[idx], y1 = sx[idx + 1];
        zr[i] = fmaf(w, y1 - y0, y0);
    }
}

// ---------------------------------------------------------------------------
// GEMM2 on fp16 tensor cores: out = warped @ fc^T + fb.
// CTA 128 rows x 112 cols, 256 threads, warps 4(m) x 2(n) -> warp 32x56.
// A (warped fp32) staged via cp.async (row stride 40 floats), split in-kernel.
// B = g_fpre fragments. 3-stage, 34816 B/stage.
// ---------------------------------------------------------------------------
#define G2_STG_B 34816
#define GEMM2_SMEM (3 * G2_STG_B)

__global__ void __launch_bounds__(256, 1)
gemm2_mma_kernel(const float* __restrict__ fb, float* __restrict__ out)
{
    extern __shared__ char smc[];
    const uint32_t smb = smem_u32(smc);
    const int tid  = threadIdx.x;
    const int lane = tid & 31;
    const int wid  = tid >> 5;
    const int wm   = wid & 3;
    const int wn   = wid >> 2;

    const int bm = blockIdx.x * 128;
    const float* gA = g_buf + (size_t)bm * NIN;
    const uint4* gB = (const uint4*)g_fpre;

    float acc[2][7][4] = {};

    #define ISSUE2(t, s) do {                                                   \
        uint32_t d = smb + (s) * G2_STG_B;                                      \
        _Pragma("unroll")                                                       \
        for (int j = 0; j < 4; ++j) {                                           \
            int idx = tid + j * 256;                                            \
            int r2 = idx >> 3, q = idx & 7;                                     \
            CP_ASYNC16(d + r2 * 160 + q * 16,                                   \
                       gA + (size_t)r2 * NIN + (t) * 32 + q * 4);               \
        }                                                                       \
        _Pragma("unroll")                                                       \
        for (int j = 0; j < 4; ++j) {                                           \
            int idx = tid + j * 256;                                            \
            if (idx < 896)                                                      \
                CP_ASYNC16(d + 20480 + idx * 16, gB + 2 * (t) * 448 + idx);     \
        }                                                                       \
        CP_COMMIT();                                                            \
    } while (0)

    ISSUE2(0, 0);
    ISSUE2(1, 1);

    for (int t = 0; t < NTS; ++t) {
        const int s = t % 3;
        if (t == NTS - 1) { CP_WAIT(0); } else { CP_WAIT(1); }
        __syncthreads();
        if (t + 2 < NTS) ISSUE2(t + 2, (t + 2) % 3);

        const float* sA = (const float*)(smc + s * G2_STG_B);
        const uint4* sB = (const uint4*)(smc + s * G2_STG_B + 20480);

        #pragma unroll
        for (int c = 0; c < 2; ++c) {
            uint4 ah[2], al[2];
            #pragma unroll
            for (int mt = 0; mt < 2; ++mt) {
                const int r = wm * 32 + mt * 16 + (lane >> 2);
                const float* p = sA + r * 40 + c * 16 + (lane & 3) * 2;
                float2 p0 = *(const float2*)(p);
                float2 p1 = *(const float2*)(p + 8 * 40);
                float2 p2 = *(const float2*)(p + 8);
                float2 p3 = *(const float2*)(p + 8 * 40 + 8);
                split2(p0.x, p0.y, ah[mt].x, al[mt].x);
                split2(p1.x, p1.y, ah[mt].y, al[mt].y);
                split2(p2.x, p2.y, ah[mt].z, al[mt].z);
                split2(p3.x, p3.y, ah[mt].w, al[mt].w);
            }
            #pragma unroll
            for (int nt = 0; nt < 7; ++nt) {
                const uint4 bv = sB[c * 448 + (wn * 7 + nt) * 32 + lane];
                #pragma unroll
                for (int mt = 0; mt < 2; ++mt) {
                    MMA_F16(acc[mt][nt], ah[mt], bv.x, bv.y);
                    MMA_F16(acc[mt][nt], al[mt], bv.x, bv.y);
                    MMA_F16(acc[mt][nt], ah[mt], bv.z, bv.w);
                }
            }
        }
    }
    #undef ISSUE2

    // epilogue
    const int r0 = lane >> 2;
    const int c0 = lane & 3;
    #pragma unroll
    for (int mt = 0; mt < 2; ++mt) {
        const int m = bm + wm * 32 + mt * 16 + r0;
        #pragma unroll
        for (int nt = 0; nt < 7; ++nt) {
            const int cidx = (wn * 7 + nt) * 8 + c0 * 2;
            if (cidx < NCLS) {
                const float2 bv = *(const float2*)(fb + cidx);
                float2 v0, v1;
                v0.x = acc[mt][nt][0] + bv.x;
                v0.y = acc[mt][nt][1] + bv.y;
                v1.x = acc[mt][nt][2] + bv.x;
                v1.y = acc[mt][nt][3] + bv.y;
                *(float2*)(out + (size_t)m * NCLS + cidx)       = v0;
                *(float2*)(out + (size_t)(m + 8) * NCLS + cidx) = v1;
            }
        }
    }
}

// ---------------------------------------------------------------------------
extern "C" void kernel_launch(void* const* d_in, const int* in_sizes, int n_in,
                              void* d_out, int out_size)
{
    const float* x  = (const float*)d_in[0];
    const float* w  = (const float*)d_in[1];
    const float* wb = (const float*)d_in[2];
    const float* fw = (const float*)d_in[3];
    const float* fb = (const float*)d_in[4];
    float* out = (float*)d_out;

    cudaFuncSetAttribute(gemm1_mma_kernel,
                         cudaFuncAttributeMaxDynamicSharedMemorySize, GEMM1_SMEM);
    cudaFuncSetAttribute(gemm2_mma_kernel,
                         cudaFuncAttributeMaxDynamicSharedMemorySize, GEMM2_SMEM);

    prep_a_kernel<<<16384, 256>>>(x);
    prep_w_kernel<<<4096, 256>>>(w);
    prep_f_kernel<<<128, 448>>>(fw);

    dim3 g1(NIN / 128, NROWS / 256);          // 16 x 64
    gemm1_mma_kernel<<<g1, 256, GEMM1_SMEM>>>(wb);
    warp_rows_kernel<<<NROWS, 256>>>(x);
    gemm2_mma_kernel<<<NROWS / 128, 256, GEMM2_SMEM>>>(fb, out);
}